// round 6
// baseline (speedup 1.0000x reference)
#include <cuda_runtime.h>
#include <cstdint>

#define SEQ   4096
#define VECT  300
#define HID   128
#define G3    384
#define NSTACK 3

typedef unsigned long long ull;
typedef long long ll;

// ---------------------------------------------------------------------------
// Scratch (static device globals — allocation-free)
// ---------------------------------------------------------------------------
__device__ float g_x    [2 * SEQ * VECT];
__device__ float g_cur  [2 * SEQ * VECT];
__device__ float g_qkv  [2ll * SEQ * 3 * VECT];   // packed [seq][row][900]: Q|K|V
__device__ float g_vt   [2 * SEQ * VECT];         // V^T per seq: [VECT][SEQ]
__device__ float g_attn [2 * SEQ * VECT];
__device__ float g_h    [2 * SEQ * VECT];
__device__ float g_tmp  [2 * SEQ * VECT];
__device__ float g_gx   [2 * SEQ * G3];
__device__ float g_hcat [2 * HID];
// packed weights
__device__ float g_wqkv [3 * VECT * VECT];
__device__ float g_bqkv [3 * VECT];
__device__ float g_wih  [2 * G3 * VECT];
__device__ float g_bih  [2 * G3];

// ---------------------------------------------------------------------------
__global__ void init_kernel(const float* __restrict__ x1, const float* __restrict__ x2)
{
    int i = blockIdx.x * blockDim.x + threadIdx.x;
    const int n = SEQ * VECT;
    if (i < n) {
        float v = x1[i];
        g_x[i] = v; g_cur[i] = v;
    } else if (i < 2 * n) {
        float v = x2[i - n];
        g_x[i] = v; g_cur[i] = v;
    }
}

// ---------------------------------------------------------------------------
__global__ void pack_kernel(
    const float* __restrict__ qw, const float* __restrict__ qb,
    const float* __restrict__ kw, const float* __restrict__ kb,
    const float* __restrict__ vw, const float* __restrict__ vb,
    const float* __restrict__ w1, const float* __restrict__ b1,
    const float* __restrict__ w2, const float* __restrict__ b2)
{
    const int N1 = 3 * VECT * VECT;
    const int N2 = 3 * VECT;
    const int N3 = 2 * G3 * VECT;
    const int N4 = 2 * G3;
    int i = blockIdx.x * blockDim.x + threadIdx.x;
    if (i < N1) {
        int row = i / VECT, col = i % VECT;
        float v;
        if (row < VECT)            v = qw[row * VECT + col];
        else if (row < 2 * VECT)   v = kw[(row - VECT) * VECT + col];
        else                       v = vw[(row - 2 * VECT) * VECT + col];
        g_wqkv[i] = v;
    } else if (i < N1 + N2) {
        int r = i - N1;
        g_bqkv[r] = (r < VECT) ? qb[r] : (r < 2 * VECT) ? kb[r - VECT] : vb[r - 2 * VECT];
    } else if (i < N1 + N2 + N3) {
        int j = i - N1 - N2;
        g_wih[j] = (j < G3 * VECT) ? w1[j] : w2[j - G3 * VECT];
    } else if (i < N1 + N2 + N3 + N4) {
        int j = i - N1 - N2 - N3;
        g_bih[j] = (j < G3) ? b1[j] : b2[j - G3];
    }
}

// ---------------------------------------------------------------------------
// Transpose: dst[c][r] = src[r][c]. src [SEQ, VECT] (ld=lds), dst [VECT][SEQ].
// ---------------------------------------------------------------------------
__global__ __launch_bounds__(256) void transpose_kernel(
    const float* __restrict__ src, float* __restrict__ dst,
    int lds, ll sSrc, ll sDst)
{
    __shared__ float t[32][33];
    src += (ll)blockIdx.z * sSrc;
    dst += (ll)blockIdx.z * sDst;
    const int r0 = blockIdx.y * 32, c0 = blockIdx.x * 32;
    const int x = threadIdx.x & 31, y = threadIdx.x >> 5;

    #pragma unroll
    for (int i = 0; i < 4; i++) {
        int col = c0 + x;
        if (col < VECT) t[y + 8 * i][x] = src[(size_t)(r0 + y + 8 * i) * lds + col];
    }
    __syncthreads();
    #pragma unroll
    for (int i = 0; i < 4; i++) {
        int c = c0 + y + 8 * i;
        if (c < VECT) dst[(size_t)c * SEQ + r0 + x] = t[x][y + 8 * i];
    }
}

// ---------------------------------------------------------------------------
// MMA helpers
// ---------------------------------------------------------------------------
__device__ __forceinline__ unsigned smem_u32(const void* p)
{
    return (unsigned)__cvta_generic_to_shared(p);
}
__device__ __forceinline__ void cp_async16(unsigned dst, const float* src, bool valid)
{
    int sz = valid ? 16 : 0;   // src-size 0 -> zero-fill 16B
    asm volatile("cp.async.cg.shared.global [%0], [%1], 16, %2;\n"
                 :: "r"(dst), "l"(src), "r"(sz));
}
__device__ __forceinline__ void ldsm_x4(uint32_t* r, unsigned addr)
{
    asm volatile("ldmatrix.sync.aligned.m8n8.x4.shared.b16 {%0,%1,%2,%3}, [%4];"
                 : "=r"(r[0]), "=r"(r[1]), "=r"(r[2]), "=r"(r[3]) : "r"(addr));
}
__device__ __forceinline__ void mma8(float* c, const uint32_t* a, const uint32_t* b)
{
    asm volatile(
        "mma.sync.aligned.m16n8k8.row.col.f32.tf32.tf32.f32 "
        "{%0,%1,%2,%3}, {%4,%5,%6,%7}, {%8,%9}, {%0,%1,%2,%3};"
        : "+f"(c[0]), "+f"(c[1]), "+f"(c[2]), "+f"(c[3])
        : "r"(a[0]), "r"(a[1]), "r"(a[2]), "r"(a[3]), "r"(b[0]), "r"(b[1]));
}

// ---------------------------------------------------------------------------
// TF32 GEMM: C[M,N] = alpha*A[M,K]*B[N,K]^T (+bias), 128x128x32, 3-stage.
// ---------------------------------------------------------------------------
__global__ __launch_bounds__(256, 2) void mma_bt(
    const float* __restrict__ A, const float* __restrict__ B, float* __restrict__ C,
    int M, int N, int K, int lda, int ldb, int ldc,
    ll sAb, ll sBb, ll sCb,
    const float* __restrict__ bias, ll sBiasb, float alpha)
{
    constexpr int BM = 128, BN = 128, BK = 32, AP = 36;
    constexpr int ASZ = BM * AP;
    constexpr int STG = 2 * ASZ;

    extern __shared__ float sm[];

    A += (ll)blockIdx.z * sAb;
    B += (ll)blockIdx.z * sBb;
    C += (ll)blockIdx.z * sCb;
    if (bias) bias += (ll)blockIdx.z * sBiasb;

    const int m0 = blockIdx.y * BM, n0 = blockIdx.x * BN;
    const int tid = threadIdx.x, lane = tid & 31, warp = tid >> 5;
    const int g = lane >> 2, tg = lane & 3;
    const int wm = (warp & 1) * 64, wn = (warp >> 1) * 32;

    const int lm   = lane >> 3;
    const int lrow = (lm & 1) * 8 + (lane & 7);
    const int lcol = (lm >> 1) * 4;

    float acc[4][4][4] = {};
    const int nk = (K + BK - 1) / BK;

    auto load_stage = [&](int s, int k0) {
        unsigned base = smem_u32(sm + s * STG);
        #pragma unroll
        for (int i = 0; i < 4; i++) {
            int idx = tid + i * 256;
            int r = idx >> 3, c = (idx & 7) * 4;
            cp_async16(base + (unsigned)(r * AP + c) * 4,
                       A + (size_t)(m0 + r) * lda + k0 + c, (k0 + c < K));
        }
        #pragma unroll
        for (int i = 0; i < 4; i++) {
            int idx = tid + i * 256;
            int r = idx >> 3, c = (idx & 7) * 4;
            bool v = (n0 + r < N) && (k0 + c < K);
            cp_async16(base + (unsigned)(ASZ + r * AP + c) * 4,
                       B + (size_t)(n0 + r) * ldb + k0 + c, v);
        }
        asm volatile("cp.async.commit_group;");
    };

    load_stage(0, 0);
    if (nk > 1) load_stage(1, BK);

    for (int kt = 0; kt < nk; kt++) {
        int s = kt % 3;
        if (kt + 1 < nk) asm volatile("cp.async.wait_group 1;");
        else             asm volatile("cp.async.wait_group 0;");
        __syncthreads();

        if (kt + 2 < nk) load_stage((kt + 2) % 3, (kt + 2) * BK);

        unsigned aBase = smem_u32(sm + s * STG)
                       + (unsigned)((wm + lrow) * AP + lcol) * 4;
        unsigned bBase = smem_u32(sm + s * STG + ASZ)
                       + (unsigned)((wn + lrow) * AP + lcol) * 4;

        #pragma unroll
        for (int kk = 0; kk < BK; kk += 8) {
            uint32_t ar[4][4];
            #pragma unroll
            for (int mt = 0; mt < 4; mt++)
                ldsm_x4(ar[mt], aBase + (unsigned)(mt * 16 * AP + kk) * 4);
            uint32_t brq[2][4];
            #pragma unroll
            for (int nh = 0; nh < 2; nh++)
                ldsm_x4(brq[nh], bBase + (unsigned)(nh * 16 * AP + kk) * 4);

            #pragma unroll
            for (int mt = 0; mt < 4; mt++) {
                #pragma unroll
                for (int nt = 0; nt < 4; nt++) {
                    uint32_t bb[2] = { brq[nt >> 1][nt & 1], brq[nt >> 1][(nt & 1) + 2] };
                    mma8(acc[mt][nt], ar[mt], bb);
                }
            }
        }
    }

    #pragma unroll
    for (int mt = 0; mt < 4; mt++) {
        #pragma unroll
        for (int nt = 0; nt < 4; nt++) {
            int row0 = m0 + wm + mt * 16 + g;
            int col  = n0 + wn + nt * 8 + 2 * tg;
            if (col + 1 < N) {
                float b0 = bias ? bias[col]     : 0.f;
                float b1 = bias ? bias[col + 1] : 0.f;
                float2 v0 = make_float2(alpha * acc[mt][nt][0] + b0,
                                        alpha * acc[mt][nt][1] + b1);
                float2 v1 = make_float2(alpha * acc[mt][nt][2] + b0,
                                        alpha * acc[mt][nt][3] + b1);
                *reinterpret_cast<float2*>(C + (size_t)row0 * ldc + col) = v0;
                *reinterpret_cast<float2*>(C + (size_t)(row0 + 8) * ldc + col) = v1;
            } else if (col < N) {
                float b0 = bias ? bias[col] : 0.f;
                C[(size_t)row0 * ldc + col]       = alpha * acc[mt][nt][0] + b0;
                C[(size_t)(row0 + 8) * ldc + col] = alpha * acc[mt][nt][2] + b0;
            }
        }
    }
}

// ---------------------------------------------------------------------------
// Flash attention: attn = softmax(Q K^T / sqrt(300)) V, never materializing S.
// Per CTA: 64 Q rows, 256 threads (8 warps = 4 m-tiles x 2 n-columns).
// Q resident in smem; K in 128-key tiles (32-dim chunks, dbuf); online softmax
// in registers (cross-warp-column exchange via smem); P staged in smem; V^T
// streamed in 64-row n-chunks (dbuf).
// ---------------------------------------------------------------------------
__global__ __launch_bounds__(256, 1) void flash_kernel(
    const float* __restrict__ qkv, const float* __restrict__ vt,
    float* __restrict__ attn)
{
    constexpr int QP = 324, KP = 36, PP = 132, VP = 132;
    constexpr int QSZ = 64 * QP;        // 20736
    constexpr int KSZ = 128 * KP;       // 4608
    constexpr int PSZ = 64 * PP;        // 8448
    constexpr int VSZ = 64 * VP;        // 8448
    const ll S9 = (ll)SEQ * 3 * VECT;
    const ll SV = (ll)SEQ * VECT;
    const float inv_scale = 0.05773502691896258f;

    extern __shared__ float sm[];
    float* Qs   = sm;
    float* Ks   = Qs + QSZ;             // 2 buffers
    float* Ps   = Ks + 2 * KSZ;
    float* Vs   = Ps + PSZ;             // 2 buffers
    float* redm = Vs + 2 * VSZ;         // 128
    float* reds = redm + 128;           // 128

    const float* Qg  = qkv + (ll)blockIdx.y * S9;
    const float* Kg  = Qg + VECT;
    const float* Vtg = vt + (ll)blockIdx.y * SV;
    float* Og        = attn + (ll)blockIdx.y * SV;
    const int q0 = blockIdx.x * 64;

    const int tid = threadIdx.x, lane = tid & 31, warp = tid >> 5;
    const int g = lane >> 2, tg = lane & 3;
    const int wm = (warp & 3) * 16;     // m offset (rows)
    const int wc = warp >> 2;           // 0/1 key-column half
    const int lm   = lane >> 3;
    const int lrow = (lm & 1) * 8 + (lane & 7);
    const int lcol = (lm >> 1) * 4;

    // ---- load Q tile (64 x 320, zero-padded past 300) ----
    {
        unsigned qb = smem_u32(Qs);
        #pragma unroll
        for (int i = 0; i < 20; i++) {
            int idx = tid + i * 256;           // 0..5119
            int r = idx / 80, c = (idx % 80) * 4;
            cp_async16(qb + (unsigned)(r * QP + c) * 4,
                       Qg + (size_t)(q0 + r) * (3 * VECT) + c, c < VECT);
        }
        asm volatile("cp.async.commit_group;");
        asm volatile("cp.async.wait_group 0;");
        __syncthreads();
    }

    auto load_k = [&](int buf, int kt, int kd) {
        unsigned kb = smem_u32(Ks + buf * KSZ);
        #pragma unroll
        for (int i = 0; i < 4; i++) {
            int idx = tid + i * 256;
            int r = idx >> 3, c = (idx & 7) * 4;
            cp_async16(kb + (unsigned)(r * KP + c) * 4,
                       Kg + (size_t)(kt * 128 + r) * (3 * VECT) + kd * 32 + c,
                       (kd * 32 + c) < VECT);
        }
        asm volatile("cp.async.commit_group;");
    };
    auto load_v = [&](int buf, int kt, int nc) {
        unsigned vb = smem_u32(Vs + buf * VSZ);
        #pragma unroll
        for (int i = 0; i < 8; i++) {
            int idx = tid + i * 256;
            int r = idx >> 5, c = (idx & 31) * 4;
            cp_async16(vb + (unsigned)(r * VP + c) * 4,
                       Vtg + (size_t)(nc * 64 + r) * SEQ + kt * 128 + c,
                       (nc * 64 + r) < VECT);
        }
        asm volatile("cp.async.commit_group;");
    };

    float O[5][4][4] = {};
    float m0 = -1e30f, m1 = -1e30f, l0 = 0.f, l1 = 0.f;

    load_k(0, 0, 0);

    for (int kt = 0; kt < 32; kt++) {
        // ---- S = Q K^T over 10 k-chunks ----
        float S[8][4] = {};
        #pragma unroll 1
        for (int kd = 0; kd < 10; kd++) {
            asm volatile("cp.async.wait_group 0;");
            __syncthreads();
            if (kd < 9) load_k((kd + 1) & 1, kt, kd + 1);

            unsigned aQ = smem_u32(Qs)
                        + (unsigned)((wm + lrow) * QP + lcol + kd * 32) * 4;
            unsigned bK = smem_u32(Ks + (kd & 1) * KSZ)
                        + (unsigned)((wc * 64 + lrow) * KP + lcol) * 4;
            #pragma unroll
            for (int kk = 0; kk < 32; kk += 8) {
                uint32_t aq[4];
                ldsm_x4(aq, aQ + (unsigned)kk * 4);
                uint32_t bq[4][4];
                #pragma unroll
                for (int nh = 0; nh < 4; nh++)
                    ldsm_x4(bq[nh], bK + (unsigned)(nh * 16 * KP + kk) * 4);
                #pragma unroll
                for (int nt = 0; nt < 8; nt++) {
                    uint32_t bb[2] = { bq[nt >> 1][nt & 1], bq[nt >> 1][(nt & 1) + 2] };
                    mma8(S[nt], aq, bb);
                }
            }
        }

        // prefetch V chunk 0 and next tile's first K chunk (overlap softmax)
        load_v(0, kt, 0);
        if (kt < 31) load_k(0, kt + 1, 0);

        // ---- online softmax ----
        #pragma unroll
        for (int nt = 0; nt < 8; nt++) {
            S[nt][0] *= inv_scale; S[nt][1] *= inv_scale;
            S[nt][2] *= inv_scale; S[nt][3] *= inv_scale;
        }
        float mx0 = -1e30f, mx1 = -1e30f;
        #pragma unroll
        for (int nt = 0; nt < 8; nt++) {
            mx0 = fmaxf(mx0, fmaxf(S[nt][0], S[nt][1]));
            mx1 = fmaxf(mx1, fmaxf(S[nt][2], S[nt][3]));
        }
        mx0 = fmaxf(mx0, __shfl_xor_sync(0xffffffffu, mx0, 1));
        mx0 = fmaxf(mx0, __shfl_xor_sync(0xffffffffu, mx0, 2));
        mx1 = fmaxf(mx1, __shfl_xor_sync(0xffffffffu, mx1, 1));
        mx1 = fmaxf(mx1, __shfl_xor_sync(0xffffffffu, mx1, 2));
        if (tg == 0) {
            redm[wc * 64 + wm + g]     = mx0;
            redm[wc * 64 + wm + g + 8] = mx1;
        }
        __syncthreads();
        float mn0 = fmaxf(m0, fmaxf(mx0, redm[(1 - wc) * 64 + wm + g]));
        float mn1 = fmaxf(m1, fmaxf(mx1, redm[(1 - wc) * 64 + wm + g + 8]));
        float a0 = __expf(m0 - mn0);
        float a1 = __expf(m1 - mn1);
        m0 = mn0; m1 = mn1;

        float rs0 = 0.f, rs1 = 0.f;
        #pragma unroll
        for (int nt = 0; nt < 8; nt++) {
            float p0 = __expf(S[nt][0] - mn0), p1 = __expf(S[nt][1] - mn0);
            float p2 = __expf(S[nt][2] - mn1), p3 = __expf(S[nt][3] - mn1);
            rs0 += p0 + p1; rs1 += p2 + p3;
            int col = wc * 64 + nt * 8 + 2 * tg;
            *reinterpret_cast<float2*>(&Ps[(wm + g) * PP + col])     = make_float2(p0, p1);
            *reinterpret_cast<float2*>(&Ps[(wm + g + 8) * PP + col]) = make_float2(p2, p3);
        }
        rs0 += __shfl_xor_sync(0xffffffffu, rs0, 1);
        rs0 += __shfl_xor_sync(0xffffffffu, rs0, 2);
        rs1 += __shfl_xor_sync(0xffffffffu, rs1, 1);
        rs1 += __shfl_xor_sync(0xffffffffu, rs1, 2);
        if (tg == 0) {
            reds[wc * 64 + wm + g]     = rs0;
            reds[wc * 64 + wm + g + 8] = rs1;
        }
        __syncthreads();
        rs0 += reds[(1 - wc) * 64 + wm + g];
        rs1 += reds[(1 - wc) * 64 + wm + g + 8];
        l0 = l0 * a0 + rs0;
        l1 = l1 * a1 + rs1;
        #pragma unroll
        for (int nc = 0; nc < 5; nc++)
            #pragma unroll
            for (int nt = 0; nt < 4; nt++) {
                O[nc][nt][0] *= a0; O[nc][nt][1] *= a0;
                O[nc][nt][2] *= a1; O[nc][nt][3] *= a1;
            }

        // ---- O += P V over 5 n-chunks of 64 ----
        #pragma unroll 1
        for (int nc = 0; nc < 5; nc++) {
            asm volatile("cp.async.wait_group 0;");
            __syncthreads();
            if (nc < 4) load_v((nc + 1) & 1, kt, nc + 1);

            unsigned aP = smem_u32(Ps)
                        + (unsigned)((wm + lrow) * PP + lcol) * 4;
            unsigned bV = smem_u32(Vs + (nc & 1) * VSZ)
                        + (unsigned)((wc * 32 + lrow) * VP + lcol) * 4;
            #pragma unroll
            for (int kk = 0; kk < 128; kk += 8) {
                uint32_t ap[4];
                ldsm_x4(ap, aP + (unsigned)kk * 4);
                uint32_t bv[2][4];
                ldsm_x4(bv[0], bV + (unsigned)kk * 4);
                ldsm_x4(bv[1], bV + (unsigned)(16 * VP + kk) * 4);
                #pragma unroll
                for (int nt = 0; nt < 4; nt++) {
                    uint32_t bb[2] = { bv[nt >> 1][nt & 1], bv[nt >> 1][(nt & 1) + 2] };
                    mma8(O[nc][nt], ap, bb);
                }
            }
        }
        __syncthreads();   // protect Ps / Vs buf0 / redm for next tile
    }

    // ---- epilogue ----
    float i0 = 1.f / l0, i1 = 1.f / l1;
    #pragma unroll
    for (int nc = 0; nc < 5; nc++) {
        #pragma unroll
        for (int nt = 0; nt < 4; nt++) {
            int col = nc * 64 + wc * 32 + nt * 8 + 2 * tg;
            if (col < VECT) {
                int r0 = q0 + wm + g;
                *reinterpret_cast<float2*>(&Og[(size_t)r0 * VECT + col]) =
                    make_float2(O[nc][nt][0] * i0, O[nc][nt][1] * i0);
                *reinterpret_cast<float2*>(&Og[(size_t)(r0 + 8) * VECT + col]) =
                    make_float2(O[nc][nt][2] * i1, O[nc][nt][3] * i1);
            }
        }
    }
}

// ---------------------------------------------------------------------------
__device__ __forceinline__ float warp_sum(float v) {
    #pragma unroll
    for (int o = 16; o > 0; o >>= 1) v += __shfl_xor_sync(0xffffffffu, v, o);
    return v;
}

__global__ __launch_bounds__(128) void ln_add_kernel(
    const float* __restrict__ s1, const float* __restrict__ s2,
    const float* __restrict__ g, const float* __restrict__ b,
    float* __restrict__ dst)
{
    const int wid = threadIdx.x >> 5, lane = threadIdx.x & 31;
    const int row = blockIdx.x * 4 + wid;
    const size_t base = ((size_t)blockIdx.y * SEQ + row) * VECT;

    float v[10];
    float s = 0.f;
    #pragma unroll
    for (int i = 0; i < 10; i++) {
        int j = lane + 32 * i;
        float x = 0.f;
        if (j < VECT) x = s1[base + j] + s2[base + j];
        v[i] = x; s += x;
    }
    s = warp_sum(s);
    float mean = s * (1.f / VECT);

    float var = 0.f;
    #pragma unroll
    for (int i = 0; i < 10; i++) {
        int j = lane + 32 * i;
        if (j < VECT) { float d = v[i] - mean; var += d * d; }
    }
    var = warp_sum(var) * (1.f / VECT);
    float inv = rsqrtf(var + 1e-5f);

    #pragma unroll
    for (int i = 0; i < 10; i++) {
        int j = lane + 32 * i;
        if (j < VECT) dst[base + j] = g[j] * (v[i] - mean) * inv + b[j];
    }
}

// ---------------------------------------------------------------------------
__global__ __launch_bounds__(384, 1) void gru_kernel(
    const float* __restrict__ whh1, const float* __restrict__ bhh1,
    const float* __restrict__ whh2, const float* __restrict__ bhh2)
{
    const int b = blockIdx.x;
    const float* whh = b ? whh2 : whh1;
    const float* bhh = b ? bhh2 : bhh1;
    const float* gx  = g_gx + (size_t)b * SEQ * G3;
    const int t = threadIdx.x;

    ull wp[64];
    const ull* w2 = reinterpret_cast<const ull*>(whh + t * HID);
    #pragma unroll
    for (int j = 0; j < 64; j++) wp[j] = w2[j];
    const float bh = bhh[t];

    __shared__ __align__(16) float hsh[HID];
    __shared__ float gsh[G3];
    float hcur = 0.f;
    if (t < HID) hsh[t] = 0.f;
    __syncthreads();

    for (int step = 0; step < SEQ; step++) {
        float xr = 0.f, xz = 0.f, xn = 0.f;
        if (t < HID) {
            const float* gr = gx + (size_t)step * G3;
            xr = gr[t]; xz = gr[t + HID]; xn = gr[t + 2 * HID];
        }

        ull a0 = 0ull, a1 = 0ull, a2 = 0ull, a3 = 0ull;
        const ulonglong2* h2 = reinterpret_cast<const ulonglong2*>(hsh);
        #pragma unroll
        for (int j = 0; j < 16; j++) {
            ulonglong2 hva = h2[2 * j];
            ulonglong2 hvb = h2[2 * j + 1];
            asm("fma.rn.f32x2 %0, %1, %2, %0;" : "+l"(a0) : "l"(wp[4 * j]),     "l"(hva.x));
            asm("fma.rn.f32x2 %0, %1, %2, %0;" : "+l"(a1) : "l"(wp[4 * j + 1]), "l"(hva.y));
            asm("fma.rn.f32x2 %0, %1, %2, %0;" : "+l"(a2) : "l"(wp[4 * j + 2]), "l"(hvb.x));
            asm("fma.rn.f32x2 %0, %1, %2, %0;" : "+l"(a3) : "l"(wp[4 * j + 3]), "l"(hvb.y));
        }
        float l0, h0, l1, h1, l2, h2f, l3, h3;
        asm("mov.b64 {%0,%1}, %2;" : "=f"(l0), "=f"(h0) : "l"(a0));
        asm("mov.b64 {%0,%1}, %2;" : "=f"(l1), "=f"(h1) : "l"(a1));
        asm("mov.b64 {%0,%1}, %2;" : "=f"(l2), "=f"(h2f) : "l"(a2));
        asm("mov.b64 {%0,%1}, %2;" : "=f"(l3), "=f"(h3) : "l"(a3));
        gsh[t] = ((l0 + h0) + (l1 + h1)) + ((l2 + h2f) + (l3 + h3)) + bh;
        __syncthreads();

        if (t < HID) {
            float r = 1.f / (1.f + __expf(-(xr + gsh[t])));
            float z = 1.f / (1.f + __expf(-(xz + gsh[t + HID])));
            float n = tanhf(xn + r * gsh[t + 2 * HID]);
            hcur = (1.f - z) * n + z * hcur;
            hsh[t] = hcur;
        }
        __syncthreads();
    }
    if (t < HID) g_hcat[b * HID + t] = hcur;
}

// ---------------------------------------------------------------------------
__global__ __launch_bounds__(256) void head_kernel(
    const float* __restrict__ fc1_w, const float* __restrict__ fc1_b,
    const float* __restrict__ fc2_w, const float* __restrict__ fc2_b,
    float* __restrict__ out)
{
    __shared__ float hs[256], ys[256], ls[3];
    const int t = threadIdx.x;
    hs[t] = g_hcat[t];
    __syncthreads();

    float acc = fc1_b[t];
    #pragma unroll 8
    for (int j = 0; j < 256; j++) acc += fc1_w[t * 256 + j] * hs[j];
    ys[t] = fmaxf(acc, 0.f);
    __syncthreads();

    if (t < 3) {
        float a = fc2_b[t];
        for (int j = 0; j < 256; j++) a += fc2_w[t * 256 + j] * ys[j];
        ls[t] = a;
    }
    __syncthreads();

    if (t == 0) {
        float m = fmaxf(ls[0], fmaxf(ls[1], ls[2]));
        float s = expf(ls[0] - m) + expf(ls[1] - m) + expf(ls[2] - m);
        float lse = m + logf(s);
        out[0] = ls[0] - lse; out[1] = ls[1] - lse; out[2] = ls[2] - lse;
    }
}

// ---------------------------------------------------------------------------
extern "C" void kernel_launch(void* const* d_in, const int* in_sizes, int n_in,
                              void* d_out, int out_size)
{
    (void)in_sizes; (void)n_in; (void)out_size;

    const float* x1     = (const float*)d_in[0];
    const float* x2     = (const float*)d_in[1];
    const float* q_w    = (const float*)d_in[2];
    const float* q_b    = (const float*)d_in[3];
    const float* k_w    = (const float*)d_in[4];
    const float* k_b    = (const float*)d_in[5];
    const float* v_w    = (const float*)d_in[6];
    const float* v_b    = (const float*)d_in[7];
    const float* aln_g  = (const float*)d_in[8];
    const float* aln_b  = (const float*)d_in[9];
    const float* w_w    = (const float*)d_in[10];
    const float* w_b    = (const float*)d_in[11];
    const float* mln_g  = (const float*)d_in[12];
    const float* mln_b  = (const float*)d_in[13];
    const float* g1_wih = (const float*)d_in[14];
    const float* g1_whh = (const float*)d_in[15];
    const float* g1_bih = (const float*)d_in[16];
    const float* g1_bhh = (const float*)d_in[17];
    const float* g2_wih = (const float*)d_in[18];
    const float* g2_whh = (const float*)d_in[19];
    const float* g2_bih = (const float*)d_in[20];
    const float* g2_bhh = (const float*)d_in[21];
    const float* fc1_w  = (const float*)d_in[22];
    const float* fc1_b  = (const float*)d_in[23];
    const float* fc2_w  = (const float*)d_in[24];
    const float* fc2_b  = (const float*)d_in[25];
    float* out = (float*)d_out;

    void *pv;
    cudaGetSymbolAddress(&pv, g_x);      float* p_x      = (float*)pv;
    cudaGetSymbolAddress(&pv, g_cur);    float* p_cur    = (float*)pv;
    cudaGetSymbolAddress(&pv, g_qkv);    float* p_qkv    = (float*)pv;
    cudaGetSymbolAddress(&pv, g_vt);     float* p_vt     = (float*)pv;
    cudaGetSymbolAddress(&pv, g_attn);   float* p_attn   = (float*)pv;
    cudaGetSymbolAddress(&pv, g_h);      float* p_h      = (float*)pv;
    cudaGetSymbolAddress(&pv, g_tmp);    float* p_tmp    = (float*)pv;
    cudaGetSymbolAddress(&pv, g_gx);     float* p_gx     = (float*)pv;
    cudaGetSymbolAddress(&pv, g_wqkv);   float* p_wqkv   = (float*)pv;
    cudaGetSymbolAddress(&pv, g_bqkv);   float* p_bqkv   = (float*)pv;
    cudaGetSymbolAddress(&pv, g_wih);    float* p_wih    = (float*)pv;
    cudaGetSymbolAddress(&pv, g_bih);    float* p_bih    = (float*)pv;

    const ll SV = (ll)SEQ * VECT;
    const ll S9 = (ll)SEQ * 3 * VECT;
    const int N9 = 3 * VECT;

    const int SMEM_MMA = 3 * (2 * 128 * 36) * 4;                         // 110592 B
    const int SMEM_FLASH = (64*324 + 2*128*36 + 64*132 + 2*64*132 + 256) * 4;  // 222208 B
    cudaFuncSetAttribute(mma_bt, cudaFuncAttributeMaxDynamicSharedMemorySize, SMEM_MMA);
    cudaFuncSetAttribute(flash_kernel, cudaFuncAttributeMaxDynamicSharedMemorySize, SMEM_FLASH);

    init_kernel<<<(2 * SEQ * VECT + 255) / 256, 256>>>(x1, x2);
    {
        int tot = 3 * VECT * VECT + 3 * VECT + 2 * G3 * VECT + 2 * G3;
        pack_kernel<<<(tot + 255) / 256, 256>>>(q_w, q_b, k_w, k_b, v_w, v_b,
                                                g1_wih, g1_bih, g2_wih, g2_bih);
    }

    dim3 gqkv(8, 32, 2);    // N=900 -> 8 tiles of 128
    dim3 gav (3, 32, 2);    // N=300
    dim3 gtr (10, 128, 2);  // V transpose
    dim3 gfl (64, 2);       // flash: 64 q-tiles x 2 seqs

    for (int s = 0; s < NSTACK; s++) {
        mma_bt<<<gqkv, 256, SMEM_MMA>>>(p_cur, p_wqkv, p_qkv, SEQ, N9, VECT,
                                        VECT, VECT, N9, SV, 0, S9,
                                        p_bqkv, 0, 1.f);
        transpose_kernel<<<gtr, 256>>>(p_qkv + 2 * VECT, p_vt, N9, S9, SV);
        flash_kernel<<<gfl, 256, SMEM_FLASH>>>(p_qkv, p_vt, p_attn);

        ln_add_kernel<<<dim3(SEQ / 4, 2), 128>>>(p_attn, p_cur, aln_g, aln_b, p_h);
        mma_bt<<<gav, 256, SMEM_MMA>>>(p_h, w_w, p_tmp, SEQ, VECT, VECT,
                                       VECT, VECT, VECT, SV, 0, SV,
                                       w_b, 0, 1.f);
        ln_add_kernel<<<dim3(SEQ / 4, 2), 128>>>(p_tmp, p_x, mln_g, mln_b, p_cur);
    }

    dim3 gg(3, 32, 2);
    mma_bt<<<gg, 256, SMEM_MMA>>>(p_cur, p_wih, p_gx, SEQ, G3, VECT,
                                  VECT, VECT, G3, SV, (ll)G3 * VECT, (ll)SEQ * G3,
                                  p_bih, G3, 1.f);
    gru_kernel<<<2, 384>>>(g1_whh, g1_bhh, g2_whh, g2_bhh);
    head_kernel<<<1, 256>>>(fc1_w, fc1_b, fc2_w, fc2_b, out);
}

// round 7
// speedup vs baseline: 1.0593x; 1.0593x over previous
#include <cuda_runtime.h>
#include <cstdint>

#define SEQ   4096
#define VECT  300
#define VPAD  384
#define HID   128
#define G3    384
#define NSTACK 3

typedef unsigned long long ull;
typedef long long ll;

// ---------------------------------------------------------------------------
// Scratch (static device globals — allocation-free, zero-initialized)
// ---------------------------------------------------------------------------
__device__ float g_x    [2 * SEQ * VECT];
__device__ float g_cur  [2 * SEQ * VECT];
__device__ float g_qkv  [2ll * SEQ * 3 * VECT];   // packed [seq][row][900]: Q|K|V
__device__ float g_vt   [2ll * VPAD * SEQ];       // V^T per seq: [384(pad)][SEQ]
__device__ float g_attnT[2ll * VPAD * SEQ];       // attn^T: [384(pad)][SEQ]
__device__ float g_attn [2 * SEQ * VECT];
__device__ float g_h    [2 * SEQ * VECT];
__device__ float g_tmp  [2 * SEQ * VECT];
__device__ float g_scores[2ll * SEQ * SEQ];
__device__ float g_gx   [2 * SEQ * G3];
__device__ float g_hcat [2 * HID];
// packed weights
__device__ float g_wqkv [3 * VECT * VECT];
__device__ float g_bqkv [3 * VECT];
__device__ float g_wih  [2 * G3 * VECT];
__device__ float g_bih  [2 * G3];

// ---------------------------------------------------------------------------
__global__ void init_kernel(const float* __restrict__ x1, const float* __restrict__ x2)
{
    int i = blockIdx.x * blockDim.x + threadIdx.x;
    const int n = SEQ * VECT;
    if (i < n) {
        float v = x1[i];
        g_x[i] = v; g_cur[i] = v;
    } else if (i < 2 * n) {
        float v = x2[i - n];
        g_x[i] = v; g_cur[i] = v;
    }
}

// ---------------------------------------------------------------------------
__global__ void pack_kernel(
    const float* __restrict__ qw, const float* __restrict__ qb,
    const float* __restrict__ kw, const float* __restrict__ kb,
    const float* __restrict__ vw, const float* __restrict__ vb,
    const float* __restrict__ w1, const float* __restrict__ b1,
    const float* __restrict__ w2, const float* __restrict__ b2)
{
    const int N1 = 3 * VECT * VECT;
    const int N2 = 3 * VECT;
    const int N3 = 2 * G3 * VECT;
    const int N4 = 2 * G3;
    int i = blockIdx.x * blockDim.x + threadIdx.x;
    if (i < N1) {
        int row = i / VECT, col = i % VECT;
        float v;
        if (row < VECT)            v = qw[row * VECT + col];
        else if (row < 2 * VECT)   v = kw[(row - VECT) * VECT + col];
        else                       v = vw[(row - 2 * VECT) * VECT + col];
        g_wqkv[i] = v;
    } else if (i < N1 + N2) {
        int r = i - N1;
        g_bqkv[r] = (r < VECT) ? qb[r] : (r < 2 * VECT) ? kb[r - VECT] : vb[r - 2 * VECT];
    } else if (i < N1 + N2 + N3) {
        int j = i - N1 - N2;
        g_wih[j] = (j < G3 * VECT) ? w1[j] : w2[j - G3 * VECT];
    } else if (i < N1 + N2 + N3 + N4) {
        int j = i - N1 - N2 - N3;
        g_bih[j] = (j < G3) ? b1[j] : b2[j - G3];
    }
}

// ---------------------------------------------------------------------------
// V transpose: dst[c][s] = src[s][c].  src rows SEQ (ld=lds), dst ld=SEQ.
// ---------------------------------------------------------------------------
__global__ __launch_bounds__(256) void transpose_kernel(
    const float* __restrict__ src, float* __restrict__ dst,
    int lds, ll sSrc, ll sDst)
{
    __shared__ float t[32][33];
    src += (ll)blockIdx.z * sSrc;
    dst += (ll)blockIdx.z * sDst;
    const int r0 = blockIdx.y * 32, c0 = blockIdx.x * 32;
    const int x = threadIdx.x & 31, y = threadIdx.x >> 5;

    #pragma unroll
    for (int i = 0; i < 4; i++) {
        int col = c0 + x;
        if (col < VECT) t[y + 8 * i][x] = src[(size_t)(r0 + y + 8 * i) * lds + col];
    }
    __syncthreads();
    #pragma unroll
    for (int i = 0; i < 4; i++) {
        int c = c0 + y + 8 * i;
        if (c < VECT) dst[(size_t)c * SEQ + r0 + x] = t[x][y + 8 * i];
    }
}

// ---------------------------------------------------------------------------
// attn[s][c] = attnT[c][s].  src [VPAD][SEQ], dst [SEQ][VECT].
// grid (SEQ/32, 10, 2), 256 threads.
// ---------------------------------------------------------------------------
__global__ __launch_bounds__(256) void transpose_back_kernel(
    const float* __restrict__ src, float* __restrict__ dst)
{
    __shared__ float t[32][33];
    src += (ll)blockIdx.z * VPAD * SEQ;
    dst += (ll)blockIdx.z * SEQ * VECT;
    const int c0 = blockIdx.y * 32, s0 = blockIdx.x * 32;
    const int x = threadIdx.x & 31, y = threadIdx.x >> 5;

    #pragma unroll
    for (int i = 0; i < 4; i++) {
        int c = c0 + y + 8 * i;                    // c < 320 <= VPAD always
        t[y + 8 * i][x] = src[(size_t)c * SEQ + s0 + x];
    }
    __syncthreads();
    #pragma unroll
    for (int i = 0; i < 4; i++) {
        int s = s0 + y + 8 * i;
        int c = c0 + x;
        if (c < VECT) dst[(size_t)s * VECT + c] = t[x][y + 8 * i];
    }
}

// ---------------------------------------------------------------------------
// MMA helpers
// ---------------------------------------------------------------------------
__device__ __forceinline__ unsigned smem_u32(const void* p)
{
    return (unsigned)__cvta_generic_to_shared(p);
}
__device__ __forceinline__ void cp_async16(unsigned dst, const float* src, bool valid)
{
    int sz = valid ? 16 : 0;   // src-size 0 -> zero-fill 16B
    asm volatile("cp.async.cg.shared.global [%0], [%1], 16, %2;\n"
                 :: "r"(dst), "l"(src), "r"(sz));
}
__device__ __forceinline__ void ldsm_x4(uint32_t* r, unsigned addr)
{
    asm volatile("ldmatrix.sync.aligned.m8n8.x4.shared.b16 {%0,%1,%2,%3}, [%4];"
                 : "=r"(r[0]), "=r"(r[1]), "=r"(r[2]), "=r"(r[3]) : "r"(addr));
}
__device__ __forceinline__ void mma8(float* c, const uint32_t* a, const uint32_t* b)
{
    asm volatile(
        "mma.sync.aligned.m16n8k8.row.col.f32.tf32.tf32.f32 "
        "{%0,%1,%2,%3}, {%4,%5,%6,%7}, {%8,%9}, {%0,%1,%2,%3};"
        : "+f"(c[0]), "+f"(c[1]), "+f"(c[2]), "+f"(c[3])
        : "r"(a[0]), "r"(a[1]), "r"(a[2]), "r"(a[3]), "r"(b[0]), "r"(b[1]));
}

// ---------------------------------------------------------------------------
// TF32 GEMM: C[M,N] = alpha*A[M,K]*B[N,K]^T (+bias), 128x128x32, 3-stage.
// M % 128 == 0 assumed (A rows unguarded).
// ---------------------------------------------------------------------------
__global__ __launch_bounds__(256, 2) void mma_bt(
    const float* __restrict__ A, const float* __restrict__ B, float* __restrict__ C,
    int M, int N, int K, int lda, int ldb, int ldc,
    ll sAb, ll sBb, ll sCb,
    const float* __restrict__ bias, ll sBiasb, float alpha)
{
    constexpr int BM = 128, BN = 128, BK = 32, AP = 36;
    constexpr int ASZ = BM * AP;
    constexpr int STG = 2 * ASZ;

    extern __shared__ float sm[];

    A += (ll)blockIdx.z * sAb;
    B += (ll)blockIdx.z * sBb;
    C += (ll)blockIdx.z * sCb;
    if (bias) bias += (ll)blockIdx.z * sBiasb;

    const int m0 = blockIdx.y * BM, n0 = blockIdx.x * BN;
    const int tid = threadIdx.x, lane = tid & 31, warp = tid >> 5;
    const int g = lane >> 2, tg = lane & 3;
    const int wm = (warp & 1) * 64, wn = (warp >> 1) * 32;

    const int lm   = lane >> 3;
    const int lrow = (lm & 1) * 8 + (lane & 7);
    const int lcol = (lm >> 1) * 4;

    float acc[4][4][4] = {};
    const int nk = (K + BK - 1) / BK;

    auto load_stage = [&](int s, int k0) {
        unsigned base = smem_u32(sm + s * STG);
        #pragma unroll
        for (int i = 0; i < 4; i++) {
            int idx = tid + i * 256;
            int r = idx >> 3, c = (idx & 7) * 4;
            cp_async16(base + (unsigned)(r * AP + c) * 4,
                       A + (size_t)(m0 + r) * lda + k0 + c, (k0 + c < K));
        }
        #pragma unroll
        for (int i = 0; i < 4; i++) {
            int idx = tid + i * 256;
            int r = idx >> 3, c = (idx & 7) * 4;
            bool v = (n0 + r < N) && (k0 + c < K);
            cp_async16(base + (unsigned)(ASZ + r * AP + c) * 4,
                       B + (size_t)(n0 + r) * ldb + k0 + c, v);
        }
        asm volatile("cp.async.commit_group;");
    };

    load_stage(0, 0);
    if (nk > 1) load_stage(1, BK);

    for (int kt = 0; kt < nk; kt++) {
        int s = kt % 3;
        if (kt + 1 < nk) asm volatile("cp.async.wait_group 1;");
        else             asm volatile("cp.async.wait_group 0;");
        __syncthreads();

        if (kt + 2 < nk) load_stage((kt + 2) % 3, (kt + 2) * BK);

        unsigned aBase = smem_u32(sm + s * STG)
                       + (unsigned)((wm + lrow) * AP + lcol) * 4;
        unsigned bBase = smem_u32(sm + s * STG + ASZ)
                       + (unsigned)((wn + lrow) * AP + lcol) * 4;

        #pragma unroll
        for (int kk = 0; kk < BK; kk += 8) {
            uint32_t ar[4][4];
            #pragma unroll
            for (int mt = 0; mt < 4; mt++)
                ldsm_x4(ar[mt], aBase + (unsigned)(mt * 16 * AP + kk) * 4);
            uint32_t brq[2][4];
            #pragma unroll
            for (int nh = 0; nh < 2; nh++)
                ldsm_x4(brq[nh], bBase + (unsigned)(nh * 16 * AP + kk) * 4);

            #pragma unroll
            for (int mt = 0; mt < 4; mt++) {
                #pragma unroll
                for (int nt = 0; nt < 4; nt++) {
                    uint32_t bb[2] = { brq[nt >> 1][nt & 1], brq[nt >> 1][(nt & 1) + 2] };
                    mma8(acc[mt][nt], ar[mt], bb);
                }
            }
        }
    }

    #pragma unroll
    for (int mt = 0; mt < 4; mt++) {
        #pragma unroll
        for (int nt = 0; nt < 4; nt++) {
            int row0 = m0 + wm + mt * 16 + g;
            int col  = n0 + wn + nt * 8 + 2 * tg;
            if (col + 1 < N) {
                float b0 = bias ? bias[col]     : 0.f;
                float b1 = bias ? bias[col + 1] : 0.f;
                float2 v0 = make_float2(alpha * acc[mt][nt][0] + b0,
                                        alpha * acc[mt][nt][1] + b1);
                float2 v1 = make_float2(alpha * acc[mt][nt][2] + b0,
                                        alpha * acc[mt][nt][3] + b1);
                *reinterpret_cast<float2*>(C + (size_t)row0 * ldc + col) = v0;
                *reinterpret_cast<float2*>(C + (size_t)(row0 + 8) * ldc + col) = v1;
            } else if (col < N) {
                float b0 = bias ? bias[col] : 0.f;
                C[(size_t)row0 * ldc + col]       = alpha * acc[mt][nt][0] + b0;
                C[(size_t)(row0 + 8) * ldc + col] = alpha * acc[mt][nt][2] + b0;
            }
        }
    }
}

// ---------------------------------------------------------------------------
__device__ __forceinline__ float warp_max(float v) {
    #pragma unroll
    for (int o = 16; o > 0; o >>= 1) v = fmaxf(v, __shfl_xor_sync(0xffffffffu, v, o));
    return v;
}
__device__ __forceinline__ float warp_sum(float v) {
    #pragma unroll
    for (int o = 16; o > 0; o >>= 1) v += __shfl_xor_sync(0xffffffffu, v, o);
    return v;
}

__global__ __launch_bounds__(256) void softmax_kernel(float* __restrict__ Sm)
{
    size_t off = ((size_t)blockIdx.y * SEQ + blockIdx.x) * SEQ;
    float4* row4 = reinterpret_cast<float4*>(Sm + off);
    const int t = threadIdx.x;
    const int lane = t & 31, wid = t >> 5;

    float4 v[4];
    #pragma unroll
    for (int i = 0; i < 4; i++) v[i] = row4[t + 256 * i];

    float m = -3.4e38f;
    #pragma unroll
    for (int i = 0; i < 4; i++)
        m = fmaxf(m, fmaxf(fmaxf(v[i].x, v[i].y), fmaxf(v[i].z, v[i].w)));

    __shared__ float red[8];
    m = warp_max(m);
    if (lane == 0) red[wid] = m;
    __syncthreads();
    float bm = red[0];
    #pragma unroll
    for (int k = 1; k < 8; k++) bm = fmaxf(bm, red[k]);

    float s = 0.f;
    #pragma unroll
    for (int i = 0; i < 4; i++) {
        v[i].x = __expf(v[i].x - bm); v[i].y = __expf(v[i].y - bm);
        v[i].z = __expf(v[i].z - bm); v[i].w = __expf(v[i].w - bm);
        s += v[i].x + v[i].y + v[i].z + v[i].w;
    }
    s = warp_sum(s);
    __syncthreads();
    if (lane == 0) red[wid] = s;
    __syncthreads();
    float bs = 0.f;
    #pragma unroll
    for (int k = 0; k < 8; k++) bs += red[k];
    float inv = 1.f / bs;

    #pragma unroll
    for (int i = 0; i < 4; i++) {
        v[i].x *= inv; v[i].y *= inv; v[i].z *= inv; v[i].w *= inv;
        row4[t + 256 * i] = v[i];
    }
}

// ---------------------------------------------------------------------------
__global__ __launch_bounds__(128) void ln_add_kernel(
    const float* __restrict__ s1, const float* __restrict__ s2,
    const float* __restrict__ g, const float* __restrict__ b,
    float* __restrict__ dst)
{
    const int wid = threadIdx.x >> 5, lane = threadIdx.x & 31;
    const int row = blockIdx.x * 4 + wid;
    const size_t base = ((size_t)blockIdx.y * SEQ + row) * VECT;

    float v[10];
    float s = 0.f;
    #pragma unroll
    for (int i = 0; i < 10; i++) {
        int j = lane + 32 * i;
        float x = 0.f;
        if (j < VECT) x = s1[base + j] + s2[base + j];
        v[i] = x; s += x;
    }
    s = warp_sum(s);
    float mean = s * (1.f / VECT);

    float var = 0.f;
    #pragma unroll
    for (int i = 0; i < 10; i++) {
        int j = lane + 32 * i;
        if (j < VECT) { float d = v[i] - mean; var += d * d; }
    }
    var = warp_sum(var) * (1.f / VECT);
    float inv = rsqrtf(var + 1e-5f);

    #pragma unroll
    for (int i = 0; i < 10; i++) {
        int j = lane + 32 * i;
        if (j < VECT) dst[base + j] = g[j] * (v[i] - mean) * inv + b[j];
    }
}

// ---------------------------------------------------------------------------
__global__ __launch_bounds__(384, 1) void gru_kernel(
    const float* __restrict__ whh1, const float* __restrict__ bhh1,
    const float* __restrict__ whh2, const float* __restrict__ bhh2)
{
    const int b = blockIdx.x;
    const float* whh = b ? whh2 : whh1;
    const float* bhh = b ? bhh2 : bhh1;
    const float* gx  = g_gx + (size_t)b * SEQ * G3;
    const int t = threadIdx.x;

    ull wp[64];
    const ull* w2 = reinterpret_cast<const ull*>(whh + t * HID);
    #pragma unroll
    for (int j = 0; j < 64; j++) wp[j] = w2[j];
    const float bh = bhh[t];

    __shared__ __align__(16) float hsh[HID];
    __shared__ float gsh[G3];
    float hcur = 0.f;
    if (t < HID) hsh[t] = 0.f;
    __syncthreads();

    for (int step = 0; step < SEQ; step++) {
        float xr = 0.f, xz = 0.f, xn = 0.f;
        if (t < HID) {
            const float* gr = gx + (size_t)step * G3;
            xr = gr[t]; xz = gr[t + HID]; xn = gr[t + 2 * HID];
        }

        ull a0 = 0ull, a1 = 0ull, a2 = 0ull, a3 = 0ull;
        const ulonglong2* h2 = reinterpret_cast<const ulonglong2*>(hsh);
        #pragma unroll
        for (int j = 0; j < 16; j++) {
            ulonglong2 hva = h2[2 * j];
            ulonglong2 hvb = h2[2 * j + 1];
            asm("fma.rn.f32x2 %0, %1, %2, %0;" : "+l"(a0) : "l"(wp[4 * j]),     "l"(hva.x));
            asm("fma.rn.f32x2 %0, %1, %2, %0;" : "+l"(a1) : "l"(wp[4 * j + 1]), "l"(hva.y));
            asm("fma.rn.f32x2 %0, %1, %2, %0;" : "+l"(a2) : "l"(wp[4 * j + 2]), "l"(hvb.x));
            asm("fma.rn.f32x2 %0, %1, %2, %0;" : "+l"(a3) : "l"(wp[4 * j + 3]), "l"(hvb.y));
        }
        float l0, h0, l1, h1, l2, h2f, l3, h3;
        asm("mov.b64 {%0,%1}, %2;" : "=f"(l0), "=f"(h0) : "l"(a0));
        asm("mov.b64 {%0,%1}, %2;" : "=f"(l1), "=f"(h1) : "l"(a1));
        asm("mov.b64 {%0,%1}, %2;" : "=f"(l2), "=f"(h2f) : "l"(a2));
        asm("mov.b64 {%0,%1}, %2;" : "=f"(l3), "=f"(h3) : "l"(a3));
        gsh[t] = ((l0 + h0) + (l1 + h1)) + ((l2 + h2f) + (l3 + h3)) + bh;
        __syncthreads();

        if (t < HID) {
            float r = 1.f / (1.f + __expf(-(xr + gsh[t])));
            float z = 1.f / (1.f + __expf(-(xz + gsh[t + HID])));
            float n = tanhf(xn + r * gsh[t + 2 * HID]);
            hcur = (1.f - z) * n + z * hcur;
            hsh[t] = hcur;
        }
        __syncthreads();
    }
    if (t < HID) g_hcat[b * HID + t] = hcur;
}

// ---------------------------------------------------------------------------
__global__ __launch_bounds__(256) void head_kernel(
    const float* __restrict__ fc1_w, const float* __restrict__ fc1_b,
    const float* __restrict__ fc2_w, const float* __restrict__ fc2_b,
    float* __restrict__ out)
{
    __shared__ float hs[256], ys[256], ls[3];
    const int t = threadIdx.x;
    hs[t] = g_hcat[t];
    __syncthreads();

    float acc = fc1_b[t];
    #pragma unroll 8
    for (int j = 0; j < 256; j++) acc += fc1_w[t * 256 + j] * hs[j];
    ys[t] = fmaxf(acc, 0.f);
    __syncthreads();

    if (t < 3) {
        float a = fc2_b[t];
        for (int j = 0; j < 256; j++) a += fc2_w[t * 256 + j] * ys[j];
        ls[t] = a;
    }
    __syncthreads();

    if (t == 0) {
        float m = fmaxf(ls[0], fmaxf(ls[1], ls[2]));
        float s = expf(ls[0] - m) + expf(ls[1] - m) + expf(ls[2] - m);
        float lse = m + logf(s);
        out[0] = ls[0] - lse; out[1] = ls[1] - lse; out[2] = ls[2] - lse;
    }
}

// ---------------------------------------------------------------------------
extern "C" void kernel_launch(void* const* d_in, const int* in_sizes, int n_in,
                              void* d_out, int out_size)
{
    (void)in_sizes; (void)n_in; (void)out_size;

    const float* x1     = (const float*)d_in[0];
    const float* x2     = (const float*)d_in[1];
    const float* q_w    = (const float*)d_in[2];
    const float* q_b    = (const float*)d_in[3];
    const float* k_w    = (const float*)d_in[4];
    const float* k_b    = (const float*)d_in[5];
    const float* v_w    = (const float*)d_in[6];
    const float* v_b    = (const float*)d_in[7];
    const float* aln_g  = (const float*)d_in[8];
    const float* aln_b  = (const float*)d_in[9];
    const float* w_w    = (const float*)d_in[10];
    const float* w_b    = (const float*)d_in[11];
    const float* mln_g  = (const float*)d_in[12];
    const float* mln_b  = (const float*)d_in[13];
    const float* g1_wih = (const float*)d_in[14];
    const float* g1_whh = (const float*)d_in[15];
    const float* g1_bih = (const float*)d_in[16];
    const float* g1_bhh = (const float*)d_in[17];
    const float* g2_wih = (const float*)d_in[18];
    const float* g2_whh = (const float*)d_in[19];
    const float* g2_bih = (const float*)d_in[20];
    const float* g2_bhh = (const float*)d_in[21];
    const float* fc1_w  = (const float*)d_in[22];
    const float* fc1_b  = (const float*)d_in[23];
    const float* fc2_w  = (const float*)d_in[24];
    const float* fc2_b  = (const float*)d_in[25];
    float* out = (float*)d_out;

    void *pv;
    cudaGetSymbolAddress(&pv, g_x);      float* p_x      = (float*)pv;
    cudaGetSymbolAddress(&pv, g_cur);    float* p_cur    = (float*)pv;
    cudaGetSymbolAddress(&pv, g_qkv);    float* p_qkv    = (float*)pv;
    cudaGetSymbolAddress(&pv, g_vt);     float* p_vt     = (float*)pv;
    cudaGetSymbolAddress(&pv, g_attnT);  float* p_attnT  = (float*)pv;
    cudaGetSymbolAddress(&pv, g_attn);   float* p_attn   = (float*)pv;
    cudaGetSymbolAddress(&pv, g_h);      float* p_h      = (float*)pv;
    cudaGetSymbolAddress(&pv, g_tmp);    float* p_tmp    = (float*)pv;
    cudaGetSymbolAddress(&pv, g_scores); float* p_scores = (float*)pv;
    cudaGetSymbolAddress(&pv, g_gx);     float* p_gx     = (float*)pv;
    cudaGetSymbolAddress(&pv, g_wqkv);   float* p_wqkv   = (float*)pv;
    cudaGetSymbolAddress(&pv, g_bqkv);   float* p_bqkv   = (float*)pv;
    cudaGetSymbolAddress(&pv, g_wih);    float* p_wih    = (float*)pv;
    cudaGetSymbolAddress(&pv, g_bih);    float* p_bih    = (float*)pv;

    const ll SV = (ll)SEQ * VECT;
    const ll S9 = (ll)SEQ * 3 * VECT;
    const ll SS = (ll)SEQ * SEQ;
    const ll SP = (ll)VPAD * SEQ;       // padded transposed-buffer stride
    const int N9 = 3 * VECT;
    const float inv_scale = 0.05773502691896258f;   // 1/sqrt(300)

    const int SMEM_MMA = 3 * (2 * 128 * 36) * 4;    // 110592 B
    cudaFuncSetAttribute(mma_bt, cudaFuncAttributeMaxDynamicSharedMemorySize, SMEM_MMA);

    init_kernel<<<(2 * SEQ * VECT + 255) / 256, 256>>>(x1, x2);
    {
        int tot = 3 * VECT * VECT + 3 * VECT + 2 * G3 * VECT + 2 * G3;
        pack_kernel<<<(tot + 255) / 256, 256>>>(q_w, q_b, k_w, k_b, v_w, v_b,
                                                g1_wih, g1_bih, g2_wih, g2_bih);
    }

    dim3 gqkv(8, 32, 2);    // QKV proj: N=900 -> 8 tiles of 128
    dim3 gqk (32, 32, 2);   // QK^T: 4096x4096
    dim3 gavT(32, 3, 2);    // attnT = Vt @ P^T : M=384(3 tiles), N=4096(32 tiles)
    dim3 gw  (3, 32, 2);    // W proj: N=300
    dim3 gtr (10, 128, 2);  // V transpose
    dim3 gtb (128, 10, 2);  // attnT -> attn transpose-back

    for (int s = 0; s < NSTACK; s++) {
        // fused Q|K|V projection -> packed [SEQ,900]
        mma_bt<<<gqkv, 256, SMEM_MMA>>>(p_cur, p_wqkv, p_qkv, SEQ, N9, VECT,
                                        VECT, VECT, N9, SV, 0, S9,
                                        p_bqkv, 0, 1.f);
        // scores = Q K^T / sqrt(300)
        mma_bt<<<gqk, 256, SMEM_MMA>>>(p_qkv, p_qkv + VECT, p_scores, SEQ, SEQ, VECT,
                                       N9, N9, SEQ, S9, S9, SS,
                                       nullptr, 0, inv_scale);
        softmax_kernel<<<dim3(SEQ, 2), 256>>>(p_scores);

        // V^T (padded to 384 rows; pad rows stay zero)
        transpose_kernel<<<gtr, 256>>>(p_qkv + 2 * VECT, p_vt, N9, S9, SP);
        // attn^T[c,s] = sum_j Vt[c,j] * P[s,j]  — P (B operand) read exactly once
        mma_bt<<<gavT, 256, SMEM_MMA>>>(p_vt, p_scores, p_attnT, VPAD, SEQ, SEQ,
                                        SEQ, SEQ, SEQ, SP, SS, SP,
                                        nullptr, 0, 1.f);
        transpose_back_kernel<<<gtb, 256>>>(p_attnT, p_attn);

        ln_add_kernel<<<dim3(SEQ / 4, 2), 128>>>(p_attn, p_cur, aln_g, aln_b, p_h);
        mma_bt<<<gw, 256, SMEM_MMA>>>(p_h, w_w, p_tmp, SEQ, VECT, VECT,
                                      VECT, VECT, VECT, SV, 0, SV,
                                      w_b, 0, 1.f);
        ln_add_kernel<<<dim3(SEQ / 4, 2), 128>>>(p_tmp, p_x, mln_g, mln_b, p_cur);
    }

    // both GRU input projections in one z=2 batched launch
    dim3 gg(3, 32, 2);
    mma_bt<<<gg, 256, SMEM_MMA>>>(p_cur, p_wih, p_gx, SEQ, G3, VECT,
                                  VECT, VECT, G3, SV, (ll)G3 * VECT, (ll)SEQ * G3,
                                  p_bih, G3, 1.f);
    gru_kernel<<<2, 384>>>(g1_whh, g1_bhh, g2_whh, g2_bhh);
    head_kernel<<<1, 256>>>(fc1_w, fc1_b, fc2_w, fc2_b, out);
}

// round 9
// speedup vs baseline: 1.1777x; 1.1118x over previous
#include <cuda_runtime.h>
#include <cstdint>

#define SEQ   4096
#define VECT  300
#define HID   128
#define G3    384
#define NSTACK 3

typedef unsigned long long ull;
typedef long long ll;

// ---------------------------------------------------------------------------
// Scratch (static device globals — allocation-free)
// ---------------------------------------------------------------------------
__device__ float g_x    [2 * SEQ * VECT];
__device__ float g_cur  [2 * SEQ * VECT];
__device__ float g_qkv  [2ll * SEQ * 3 * VECT];   // packed [seq][row][900]: Q|K|V
__device__ float g_vt   [2 * SEQ * VECT];         // V^T per seq: [VECT][SEQ]
__device__ float g_attn [2 * SEQ * VECT];
__device__ float g_h    [2 * SEQ * VECT];
__device__ float g_tmp  [2 * SEQ * VECT];
__device__ float g_scores[2ll * SEQ * SEQ];
__device__ float g_gx   [2 * SEQ * G3];
__device__ float g_hcat [2 * HID];
// packed weights
__device__ float g_wqkv [3 * VECT * VECT];
__device__ float g_bqkv [3 * VECT];
__device__ float g_wih  [2 * G3 * VECT];
__device__ float g_bih  [2 * G3];

// ---------------------------------------------------------------------------
__global__ void init_kernel(const float* __restrict__ x1, const float* __restrict__ x2)
{
    int i = blockIdx.x * blockDim.x + threadIdx.x;
    const int n = SEQ * VECT;
    if (i < n) {
        float v = x1[i];
        g_x[i] = v; g_cur[i] = v;
    } else if (i < 2 * n) {
        float v = x2[i - n];
        g_x[i] = v; g_cur[i] = v;
    }
}

// ---------------------------------------------------------------------------
__global__ void pack_kernel(
    const float* __restrict__ qw, const float* __restrict__ qb,
    const float* __restrict__ kw, const float* __restrict__ kb,
    const float* __restrict__ vw, const float* __restrict__ vb,
    const float* __restrict__ w1, const float* __restrict__ b1,
    const float* __restrict__ w2, const float* __restrict__ b2)
{
    const int N1 = 3 * VECT * VECT;
    const int N2 = 3 * VECT;
    const int N3 = 2 * G3 * VECT;
    const int N4 = 2 * G3;
    int i = blockIdx.x * blockDim.x + threadIdx.x;
    if (i < N1) {
        int row = i / VECT, col = i % VECT;
        float v;
        if (row < VECT)            v = qw[row * VECT + col];
        else if (row < 2 * VECT)   v = kw[(row - VECT) * VECT + col];
        else                       v = vw[(row - 2 * VECT) * VECT + col];
        g_wqkv[i] = v;
    } else if (i < N1 + N2) {
        int r = i - N1;
        g_bqkv[r] = (r < VECT) ? qb[r] : (r < 2 * VECT) ? kb[r - VECT] : vb[r - 2 * VECT];
    } else if (i < N1 + N2 + N3) {
        int j = i - N1 - N2;
        g_wih[j] = (j < G3 * VECT) ? w1[j] : w2[j - G3 * VECT];
    } else if (i < N1 + N2 + N3 + N4) {
        int j = i - N1 - N2 - N3;
        g_bih[j] = (j < G3) ? b1[j] : b2[j - G3];
    }
}

// ---------------------------------------------------------------------------
// Transpose: dst[c][r] = src[r][c]. src [SEQ, VECT] (ld=lds), dst [VECT][SEQ].
// ---------------------------------------------------------------------------
__global__ __launch_bounds__(256) void transpose_kernel(
    const float* __restrict__ src, float* __restrict__ dst,
    int lds, ll sSrc, ll sDst)
{
    __shared__ float t[32][33];
    src += (ll)blockIdx.z * sSrc;
    dst += (ll)blockIdx.z * sDst;
    const int r0 = blockIdx.y * 32, c0 = blockIdx.x * 32;
    const int x = threadIdx.x & 31, y = threadIdx.x >> 5;

    #pragma unroll
    for (int i = 0; i < 4; i++) {
        int col = c0 + x;
        if (col < VECT) t[y + 8 * i][x] = src[(size_t)(r0 + y + 8 * i) * lds + col];
    }
    __syncthreads();
    #pragma unroll
    for (int i = 0; i < 4; i++) {
        int c = c0 + y + 8 * i;
        if (c < VECT) dst[(size_t)c * SEQ + r0 + x] = t[x][y + 8 * i];
    }
}

// ---------------------------------------------------------------------------
// MMA helpers
// ---------------------------------------------------------------------------
__device__ __forceinline__ unsigned smem_u32(const void* p)
{
    return (unsigned)__cvta_generic_to_shared(p);
}
__device__ __forceinline__ void cp_async16(unsigned dst, const float* src, bool valid)
{
    int sz = valid ? 16 : 0;   // src-size 0 -> zero-fill 16B
    asm volatile("cp.async.cg.shared.global [%0], [%1], 16, %2;\n"
                 :: "r"(dst), "l"(src), "r"(sz));
}
__device__ __forceinline__ void ldsm_x4(uint32_t* r, unsigned addr)
{
    asm volatile("ldmatrix.sync.aligned.m8n8.x4.shared.b16 {%0,%1,%2,%3}, [%4];"
                 : "=r"(r[0]), "=r"(r[1]), "=r"(r[2]), "=r"(r[3]) : "r"(addr));
}
__device__ __forceinline__ void mma8(float* c, const uint32_t* a, const uint32_t* b)
{
    asm volatile(
        "mma.sync.aligned.m16n8k8.row.col.f32.tf32.tf32.f32 "
        "{%0,%1,%2,%3}, {%4,%5,%6,%7}, {%8,%9}, {%0,%1,%2,%3};"
        : "+f"(c[0]), "+f"(c[1]), "+f"(c[2]), "+f"(c[3])
        : "r"(a[0]), "r"(a[1]), "r"(a[2]), "r"(a[3]), "r"(b[0]), "r"(b[1]));
}

// ---------------------------------------------------------------------------
// TF32 GEMM: C[M,N] = alpha*A[M,K]*B[N,K]^T (+bias), 128x128x32, 3-stage.
// M % 128 == 0 assumed.
// ---------------------------------------------------------------------------
__global__ __launch_bounds__(256, 2) void mma_bt(
    const float* __restrict__ A, const float* __restrict__ B, float* __restrict__ C,
    int M, int N, int K, int lda, int ldb, int ldc,
    ll sAb, ll sBb, ll sCb,
    const float* __restrict__ bias, ll sBiasb, float alpha)
{
    constexpr int BM = 128, BN = 128, BK = 32, AP = 36;
    constexpr int ASZ = BM * AP;
    constexpr int STG = 2 * ASZ;

    extern __shared__ float sm[];

    A += (ll)blockIdx.z * sAb;
    B += (ll)blockIdx.z * sBb;
    C += (ll)blockIdx.z * sCb;
    if (bias) bias += (ll)blockIdx.z * sBiasb;

    const int m0 = blockIdx.y * BM, n0 = blockIdx.x * BN;
    const int tid = threadIdx.x, lane = tid & 31, warp = tid >> 5;
    const int g = lane >> 2, tg = lane & 3;
    const int wm = (warp & 1) * 64, wn = (warp >> 1) * 32;

    const int lm   = lane >> 3;
    const int lrow = (lm & 1) * 8 + (lane & 7);
    const int lcol = (lm >> 1) * 4;

    float acc[4][4][4] = {};
    const int nk = (K + BK - 1) / BK;

    auto load_stage = [&](int s, int k0) {
        unsigned base = smem_u32(sm + s * STG);
        #pragma unroll
        for (int i = 0; i < 4; i++) {
            int idx = tid + i * 256;
            int r = idx >> 3, c = (idx & 7) * 4;
            cp_async16(base + (unsigned)(r * AP + c) * 4,
                       A + (size_t)(m0 + r) * lda + k0 + c, (k0 + c < K));
        }
        #pragma unroll
        for (int i = 0; i < 4; i++) {
            int idx = tid + i * 256;
            int r = idx >> 3, c = (idx & 7) * 4;
            bool v = (n0 + r < N) && (k0 + c < K);
            cp_async16(base + (unsigned)(ASZ + r * AP + c) * 4,
                       B + (size_t)(n0 + r) * ldb + k0 + c, v);
        }
        asm volatile("cp.async.commit_group;");
    };

    load_stage(0, 0);
    if (nk > 1) load_stage(1, BK);

    for (int kt = 0; kt < nk; kt++) {
        int s = kt % 3;
        if (kt + 1 < nk) asm volatile("cp.async.wait_group 1;");
        else             asm volatile("cp.async.wait_group 0;");
        __syncthreads();

        if (kt + 2 < nk) load_stage((kt + 2) % 3, (kt + 2) * BK);

        unsigned aBase = smem_u32(sm + s * STG)
                       + (unsigned)((wm + lrow) * AP + lcol) * 4;
        unsigned bBase = smem_u32(sm + s * STG + ASZ)
                       + (unsigned)((wn + lrow) * AP + lcol) * 4;

        #pragma unroll
        for (int kk = 0; kk < BK; kk += 8) {
            uint32_t ar[4][4];
            #pragma unroll
            for (int mt = 0; mt < 4; mt++)
                ldsm_x4(ar[mt], aBase + (unsigned)(mt * 16 * AP + kk) * 4);
            uint32_t brq[2][4];
            #pragma unroll
            for (int nh = 0; nh < 2; nh++)
                ldsm_x4(brq[nh], bBase + (unsigned)(nh * 16 * AP + kk) * 4);

            #pragma unroll
            for (int mt = 0; mt < 4; mt++) {
                #pragma unroll
                for (int nt = 0; nt < 4; nt++) {
                    uint32_t bb[2] = { brq[nt >> 1][nt & 1], brq[nt >> 1][(nt & 1) + 2] };
                    mma8(acc[mt][nt], ar[mt], bb);
                }
            }
        }
    }

    #pragma unroll
    for (int mt = 0; mt < 4; mt++) {
        #pragma unroll
        for (int nt = 0; nt < 4; nt++) {
            int row0 = m0 + wm + mt * 16 + g;
            int col  = n0 + wn + nt * 8 + 2 * tg;
            if (col + 1 < N) {
                float b0 = bias ? bias[col]     : 0.f;
                float b1 = bias ? bias[col + 1] : 0.f;
                float2 v0 = make_float2(alpha * acc[mt][nt][0] + b0,
                                        alpha * acc[mt][nt][1] + b1);
                float2 v1 = make_float2(alpha * acc[mt][nt][2] + b0,
                                        alpha * acc[mt][nt][3] + b1);
                *reinterpret_cast<float2*>(C + (size_t)row0 * ldc + col) = v0;
                *reinterpret_cast<float2*>(C + (size_t)(row0 + 8) * ldc + col) = v1;
            } else if (col < N) {
                float b0 = bias ? bias[col] : 0.f;
                C[(size_t)row0 * ldc + col]       = alpha * acc[mt][nt][0] + b0;
                C[(size_t)(row0 + 8) * ldc + col] = alpha * acc[mt][nt][2] + b0;
            }
        }
    }
}

// ---------------------------------------------------------------------------
__device__ __forceinline__ float warp_max(float v) {
    #pragma unroll
    for (int o = 16; o > 0; o >>= 1) v = fmaxf(v, __shfl_xor_sync(0xffffffffu, v, o));
    return v;
}
__device__ __forceinline__ float warp_sum(float v) {
    #pragma unroll
    for (int o = 16; o > 0; o >>= 1) v += __shfl_xor_sync(0xffffffffu, v, o);
    return v;
}

__global__ __launch_bounds__(256) void softmax_kernel(float* __restrict__ Sm)
{
    size_t off = ((size_t)blockIdx.y * SEQ + blockIdx.x) * SEQ;
    float4* row4 = reinterpret_cast<float4*>(Sm + off);
    const int t = threadIdx.x;
    const int lane = t & 31, wid = t >> 5;

    float4 v[4];
    #pragma unroll
    for (int i = 0; i < 4; i++) v[i] = row4[t + 256 * i];

    float m = -3.4e38f;
    #pragma unroll
    for (int i = 0; i < 4; i++)
        m = fmaxf(m, fmaxf(fmaxf(v[i].x, v[i].y), fmaxf(v[i].z, v[i].w)));

    __shared__ float red[8];
    m = warp_max(m);
    if (lane == 0) red[wid] = m;
    __syncthreads();
    float bm = red[0];
    #pragma unroll
    for (int k = 1; k < 8; k++) bm = fmaxf(bm, red[k]);

    float s = 0.f;
    #pragma unroll
    for (int i = 0; i < 4; i++) {
        v[i].x = __expf(v[i].x - bm); v[i].y = __expf(v[i].y - bm);
        v[i].z = __expf(v[i].z - bm); v[i].w = __expf(v[i].w - bm);
        s += v[i].x + v[i].y + v[i].z + v[i].w;
    }
    s = warp_sum(s);
    __syncthreads();
    if (lane == 0) red[wid] = s;
    __syncthreads();
    float bs = 0.f;
    #pragma unroll
    for (int k = 0; k < 8; k++) bs += red[k];
    float inv = 1.f / bs;

    #pragma unroll
    for (int i = 0; i < 4; i++) {
        v[i].x *= inv; v[i].y *= inv; v[i].z *= inv; v[i].w *= inv;
        row4[t + 256 * i] = v[i];
    }
}

// ---------------------------------------------------------------------------
__global__ __launch_bounds__(128) void ln_add_kernel(
    const float* __restrict__ s1, const float* __restrict__ s2,
    const float* __restrict__ g, const float* __restrict__ b,
    float* __restrict__ dst)
{
    const int wid = threadIdx.x >> 5, lane = threadIdx.x & 31;
    const int row = blockIdx.x * 4 + wid;
    const size_t base = ((size_t)blockIdx.y * SEQ + row) * VECT;

    float v[10];
    float s = 0.f;
    #pragma unroll
    for (int i = 0; i < 10; i++) {
        int j = lane + 32 * i;
        float x = 0.f;
        if (j < VECT) x = s1[base + j] + s2[base + j];
        v[i] = x; s += x;
    }
    s = warp_sum(s);
    float mean = s * (1.f / VECT);

    float var = 0.f;
    #pragma unroll
    for (int i = 0; i < 10; i++) {
        int j = lane + 32 * i;
        if (j < VECT) { float d = v[i] - mean; var += d * d; }
    }
    var = warp_sum(var) * (1.f / VECT);
    float inv = rsqrtf(var + 1e-5f);

    #pragma unroll
    for (int i = 0; i < 10; i++) {
        int j = lane + 32 * i;
        if (j < VECT) dst[base + j] = g[j] * (v[i] - mean) * inv + b[j];
    }
}

// ---------------------------------------------------------------------------
// GRU recurrence. 2 blocks (one per GRU), 384 threads.
// Optimized: gx prefetched into a 16-step smem ring (cp.async), fast
// EX2/RCP-based sigmoid/tanh, 4 independent FFMA2 accumulator chains.
// ---------------------------------------------------------------------------
__global__ __launch_bounds__(384, 1) void gru_kernel(
    const float* __restrict__ whh1, const float* __restrict__ bhh1,
    const float* __restrict__ whh2, const float* __restrict__ bhh2)
{
    const int b = blockIdx.x;
    const float* whh = b ? whh2 : whh1;
    const float* bhh = b ? bhh2 : bhh1;
    const float* gx  = g_gx + (size_t)b * SEQ * G3;
    const int t = threadIdx.x;

    ull wp[64];
    const ull* w2 = reinterpret_cast<const ull*>(whh + t * HID);
    #pragma unroll
    for (int j = 0; j < 64; j++) wp[j] = w2[j];
    const float bh = bhh[t];

    __shared__ __align__(16) float hsh[HID];
    __shared__ float gsh[G3];
    __shared__ __align__(16) float gxs[16][G3];   // 16-step input ring (24 KB)

    float hcur = 0.f;
    if (t < HID) hsh[t] = 0.f;

    // Preload 14 steps of gx into the ring (one commit group per step).
    #pragma unroll 1
    for (int s = 0; s < 14; s++) {
        if (t < 96)
            cp_async16(smem_u32(&gxs[s][t * 4]), gx + (size_t)s * G3 + t * 4, true);
        asm volatile("cp.async.commit_group;");
    }
    __syncthreads();

    #pragma unroll 1
    for (int step = 0; step < SEQ; step++) {
        // issue prefetch for step+14 (empty group near the end keeps counts aligned)
        if (t < 96 && step + 14 < SEQ)
            cp_async16(smem_u32(&gxs[(step + 14) & 15][t * 4]),
                       gx + (size_t)(step + 14) * G3 + t * 4, true);
        asm volatile("cp.async.commit_group;");

        // gh_t = dot(whh_t, h) + bhh_t  (4 independent FFMA2 chains)
        ull a0 = 0ull, a1 = 0ull, a2 = 0ull, a3 = 0ull;
        const ulonglong2* h2 = reinterpret_cast<const ulonglong2*>(hsh);
        #pragma unroll
        for (int j = 0; j < 16; j++) {
            ulonglong2 hva = h2[2 * j];
            ulonglong2 hvb = h2[2 * j + 1];
            asm("fma.rn.f32x2 %0, %1, %2, %0;" : "+l"(a0) : "l"(wp[4 * j]),     "l"(hva.x));
            asm("fma.rn.f32x2 %0, %1, %2, %0;" : "+l"(a1) : "l"(wp[4 * j + 1]), "l"(hva.y));
            asm("fma.rn.f32x2 %0, %1, %2, %0;" : "+l"(a2) : "l"(wp[4 * j + 2]), "l"(hvb.x));
            asm("fma.rn.f32x2 %0, %1, %2, %0;" : "+l"(a3) : "l"(wp[4 * j + 3]), "l"(hvb.y));
        }
        float l0, h0, l1, h1, l2, h2f, l3, h3;
        asm("mov.b64 {%0,%1}, %2;" : "=f"(l0), "=f"(h0) : "l"(a0));
        asm("mov.b64 {%0,%1}, %2;" : "=f"(l1), "=f"(h1) : "l"(a1));
        asm("mov.b64 {%0,%1}, %2;" : "=f"(l2), "=f"(h2f) : "l"(a2));
        asm("mov.b64 {%0,%1}, %2;" : "=f"(l3), "=f"(h3) : "l"(a3));
        gsh[t] = ((l0 + h0) + (l1 + h1)) + ((l2 + h2f) + (l3 + h3)) + bh;

        asm volatile("cp.async.wait_group 14;");   // gxs[step] landed (producer side)
        __syncthreads();                           // gsh + gxs visible to all

        if (t < HID) {
            const float* gr = gxs[step & 15];
            float xr = gr[t], xz = gr[t + HID], xn = gr[t + 2 * HID];
            // sigmoid via EX2 + RCP
            float r = __fdividef(1.f, 1.f + __expf(-(xr + gsh[t])));
            float z = __fdividef(1.f, 1.f + __expf(-(xz + gsh[t + HID])));
            // tanh(x) = 1 - 2/(exp(2x)+1)
            float narg = xn + r * gsh[t + 2 * HID];
            float e2 = __expf(2.f * narg);
            float n = 1.f - __fdividef(2.f, e2 + 1.f);
            hcur = n + z * (hcur - n);
            hsh[t] = hcur;
        }
        __syncthreads();
    }
    if (t < HID) g_hcat[b * HID + t] = hcur;
}

// ---------------------------------------------------------------------------
__global__ __launch_bounds__(256) void head_kernel(
    const float* __restrict__ fc1_w, const float* __restrict__ fc1_b,
    const float* __restrict__ fc2_w, const float* __restrict__ fc2_b,
    float* __restrict__ out)
{
    __shared__ float hs[256], ys[256], ls[3];
    const int t = threadIdx.x;
    hs[t] = g_hcat[t];
    __syncthreads();

    float acc = fc1_b[t];
    #pragma unroll 8
    for (int j = 0; j < 256; j++) acc += fc1_w[t * 256 + j] * hs[j];
    ys[t] = fmaxf(acc, 0.f);
    __syncthreads();

    if (t < 3) {
        float a = fc2_b[t];
        for (int j = 0; j < 256; j++) a += fc2_w[t * 256 + j] * ys[j];
        ls[t] = a;
    }
    __syncthreads();

    if (t == 0) {
        float m = fmaxf(ls[0], fmaxf(ls[1], ls[2]));
        float s = expf(ls[0] - m) + expf(ls[1] - m) + expf(ls[2] - m);
        float lse = m + logf(s);
        out[0] = ls[0] - lse; out[1] = ls[1] - lse; out[2] = ls[2] - lse;
    }
}

// ---------------------------------------------------------------------------
extern "C" void kernel_launch(void* const* d_in, const int* in_sizes, int n_in,
                              void* d_out, int out_size)
{
    (void)in_sizes; (void)n_in; (void)out_size;

    const float* x1     = (const float*)d_in[0];
    const float* x2     = (const float*)d_in[1];
    const float* q_w    = (const float*)d_in[2];
    const float* q_b    = (const float*)d_in[3];
    const float* k_w    = (const float*)d_in[4];
    const float* k_b    = (const float*)d_in[5];
    const float* v_w    = (const float*)d_in[6];
    const float* v_b    = (const float*)d_in[7];
    const float* aln_g  = (const float*)d_in[8];
    const float* aln_b  = (const float*)d_in[9];
    const float* w_w    = (const float*)d_in[10];
    const float* w_b    = (const float*)d_in[11];
    const float* mln_g  = (const float*)d_in[12];
    const float* mln_b  = (const float*)d_in[13];
    const float* g1_wih = (const float*)d_in[14];
    const float* g1_whh = (const float*)d_in[15];
    const float* g1_bih = (const float*)d_in[16];
    const float* g1_bhh = (const float*)d_in[17];
    const float* g2_wih = (const float*)d_in[18];
    const float* g2_whh = (const float*)d_in[19];
    const float* g2_bih = (const float*)d_in[20];
    const float* g2_bhh = (const float*)d_in[21];
    const float* fc1_w  = (const float*)d_in[22];
    const float* fc1_b  = (const float*)d_in[23];
    const float* fc2_w  = (const float*)d_in[24];
    const float* fc2_b  = (const float*)d_in[25];
    float* out = (float*)d_out;

    void *pv;
    cudaGetSymbolAddress(&pv, g_x);      float* p_x      = (float*)pv;
    cudaGetSymbolAddress(&pv, g_cur);    float* p_cur    = (float*)pv;
    cudaGetSymbolAddress(&pv, g_qkv);    float* p_qkv    = (float*)pv;
    cudaGetSymbolAddress(&pv, g_vt);     float* p_vt     = (float*)pv;
    cudaGetSymbolAddress(&pv, g_attn);   float* p_attn   = (float*)pv;
    cudaGetSymbolAddress(&pv, g_h);      float* p_h      = (float*)pv;
    cudaGetSymbolAddress(&pv, g_tmp);    float* p_tmp    = (float*)pv;
    cudaGetSymbolAddress(&pv, g_scores); float* p_scores = (float*)pv;
    cudaGetSymbolAddress(&pv, g_gx);     float* p_gx     = (float*)pv;
    cudaGetSymbolAddress(&pv, g_wqkv);   float* p_wqkv   = (float*)pv;
    cudaGetSymbolAddress(&pv, g_bqkv);   float* p_bqkv   = (float*)pv;
    cudaGetSymbolAddress(&pv, g_wih);    float* p_wih    = (float*)pv;
    cudaGetSymbolAddress(&pv, g_bih);    float* p_bih    = (float*)pv;

    const ll SV = (ll)SEQ * VECT;
    const ll S9 = (ll)SEQ * 3 * VECT;
    const ll SS = (ll)SEQ * SEQ;
    const int N9 = 3 * VECT;
    const float inv_scale = 0.05773502691896258f;   // 1/sqrt(300)

    const int SMEM_MMA = 3 * (2 * 128 * 36) * 4;    // 110592 B
    cudaFuncSetAttribute(mma_bt, cudaFuncAttributeMaxDynamicSharedMemorySize, SMEM_MMA);

    init_kernel<<<(2 * SEQ * VECT + 255) / 256, 256>>>(x1, x2);
    {
        int tot = 3 * VECT * VECT + 3 * VECT + 2 * G3 * VECT + 2 * G3;
        pack_kernel<<<(tot + 255) / 256, 256>>>(q_w, q_b, k_w, k_b, v_w, v_b,
                                                g1_wih, g1_bih, g2_wih, g2_bih);
    }

    dim3 gqkv(8, 32, 2);    // QKV proj: N=900 -> 8 tiles of 128
    dim3 gqk (32, 32, 2);   // QK^T: 4096x4096
    dim3 gav (3, 32, 2);    // A·V: N=300
    dim3 gw  (3, 32, 2);    // W proj
    dim3 gtr (10, 128, 2);  // V transpose

    for (int s = 0; s < NSTACK; s++) {
        mma_bt<<<gqkv, 256, SMEM_MMA>>>(p_cur, p_wqkv, p_qkv, SEQ, N9, VECT,
                                        VECT, VECT, N9, SV, 0, S9,
                                        p_bqkv, 0, 1.f);
        mma_bt<<<gqk, 256, SMEM_MMA>>>(p_qkv, p_qkv + VECT, p_scores, SEQ, SEQ, VECT,
                                       N9, N9, SEQ, S9, S9, SS,
                                       nullptr, 0, inv_scale);
        softmax_kernel<<<dim3(SEQ, 2), 256>>>(p_scores);

        transpose_kernel<<<gtr, 256>>>(p_qkv + 2 * VECT, p_vt, N9, S9, SV);
        mma_bt<<<gav, 256, SMEM_MMA>>>(p_scores, p_vt, p_attn, SEQ, VECT, SEQ,
                                       SEQ, SEQ, VECT, SS, SV, SV,
                                       nullptr, 0, 1.f);

        ln_add_kernel<<<dim3(SEQ / 4, 2), 128>>>(p_attn, p_cur, aln_g, aln_b, p_h);
        mma_bt<<<gw, 256, SMEM_MMA>>>(p_h, w_w, p_tmp, SEQ, VECT, VECT,
                                      VECT, VECT, VECT, SV, 0, SV,
                                      w_b, 0, 1.f);
        ln_add_kernel<<<dim3(SEQ / 4, 2), 128>>>(p_tmp, p_x, mln_g, mln_b, p_cur);
    }

    dim3 gg(3, 32, 2);
    mma_bt<<<gg, 256, SMEM_MMA>>>(p_cur, p_wih, p_gx, SEQ, G3, VECT,
                                  VECT, VECT, G3, SV, (ll)G3 * VECT, (ll)SEQ * G3,
                                  p_bih, G3, 1.f);
    gru_kernel<<<2, 384>>>(g1_whh, g1_bhh, g2_whh, g2_bhh);
    head_kernel<<<1, 256>>>(fc1_w, fc1_b, fc2_w, fc2_b, out);
}

// round 10
// speedup vs baseline: 1.2272x; 1.0420x over previous
#include <cuda_runtime.h>
#include <cstdint>

#define SEQ   4096
#define VECT  300
#define HID   128
#define G3    384
#define NSTACK 3

typedef unsigned long long ull;
typedef long long ll;

// ---------------------------------------------------------------------------
// Scratch (static device globals — allocation-free)
// ---------------------------------------------------------------------------
__device__ float g_x    [2 * SEQ * VECT];
__device__ float g_cur  [2 * SEQ * VECT];
__device__ float g_qkv  [2ll * SEQ * 3 * VECT];   // packed [seq][row][900]: Q|K|V
__device__ float g_vt   [2 * SEQ * VECT];         // V^T per seq: [VECT][SEQ]
__device__ float g_attn [2 * SEQ * VECT];
__device__ float g_h    [2 * SEQ * VECT];
__device__ float g_tmp  [2 * SEQ * VECT];
__device__ float g_scores[2ll * SEQ * SEQ];
__device__ float g_gx   [2 * SEQ * G3];
__device__ float g_hcat [2 * HID];
// packed weights
__device__ float g_wqkv [3 * VECT * VECT];
__device__ float g_bqkv [3 * VECT];
__device__ float g_wih  [2 * G3 * VECT];
__device__ float g_bih  [2 * G3];

// ---------------------------------------------------------------------------
__global__ void init_kernel(const float* __restrict__ x1, const float* __restrict__ x2)
{
    int i = blockIdx.x * blockDim.x + threadIdx.x;
    const int n = SEQ * VECT;
    if (i < n) {
        float v = x1[i];
        g_x[i] = v; g_cur[i] = v;
    } else if (i < 2 * n) {
        float v = x2[i - n];
        g_x[i] = v; g_cur[i] = v;
    }
}

// ---------------------------------------------------------------------------
__global__ void pack_kernel(
    const float* __restrict__ qw, const float* __restrict__ qb,
    const float* __restrict__ kw, const float* __restrict__ kb,
    const float* __restrict__ vw, const float* __restrict__ vb,
    const float* __restrict__ w1, const float* __restrict__ b1,
    const float* __restrict__ w2, const float* __restrict__ b2)
{
    const int N1 = 3 * VECT * VECT;
    const int N2 = 3 * VECT;
    const int N3 = 2 * G3 * VECT;
    const int N4 = 2 * G3;
    int i = blockIdx.x * blockDim.x + threadIdx.x;
    if (i < N1) {
        int row = i / VECT, col = i % VECT;
        float v;
        if (row < VECT)            v = qw[row * VECT + col];
        else if (row < 2 * VECT)   v = kw[(row - VECT) * VECT + col];
        else                       v = vw[(row - 2 * VECT) * VECT + col];
        g_wqkv[i] = v;
    } else if (i < N1 + N2) {
        int r = i - N1;
        g_bqkv[r] = (r < VECT) ? qb[r] : (r < 2 * VECT) ? kb[r - VECT] : vb[r - 2 * VECT];
    } else if (i < N1 + N2 + N3) {
        int j = i - N1 - N2;
        g_wih[j] = (j < G3 * VECT) ? w1[j] : w2[j - G3 * VECT];
    } else if (i < N1 + N2 + N3 + N4) {
        int j = i - N1 - N2 - N3;
        g_bih[j] = (j < G3) ? b1[j] : b2[j - G3];
    }
}

// ---------------------------------------------------------------------------
// Transpose: dst[c][r] = src[r][c]. src [SEQ, VECT] (ld=lds), dst [VECT][SEQ].
// ---------------------------------------------------------------------------
__global__ __launch_bounds__(256) void transpose_kernel(
    const float* __restrict__ src, float* __restrict__ dst,
    int lds, ll sSrc, ll sDst)
{
    __shared__ float t[32][33];
    src += (ll)blockIdx.z * sSrc;
    dst += (ll)blockIdx.z * sDst;
    const int r0 = blockIdx.y * 32, c0 = blockIdx.x * 32;
    const int x = threadIdx.x & 31, y = threadIdx.x >> 5;

    #pragma unroll
    for (int i = 0; i < 4; i++) {
        int col = c0 + x;
        if (col < VECT) t[y + 8 * i][x] = src[(size_t)(r0 + y + 8 * i) * lds + col];
    }
    __syncthreads();
    #pragma unroll
    for (int i = 0; i < 4; i++) {
        int c = c0 + y + 8 * i;
        if (c < VECT) dst[(size_t)c * SEQ + r0 + x] = t[x][y + 8 * i];
    }
}

// ---------------------------------------------------------------------------
// MMA helpers
// ---------------------------------------------------------------------------
__device__ __forceinline__ unsigned smem_u32(const void* p)
{
    return (unsigned)__cvta_generic_to_shared(p);
}
__device__ __forceinline__ void cp_async16(unsigned dst, const float* src, bool valid)
{
    int sz = valid ? 16 : 0;   // src-size 0 -> zero-fill 16B
    asm volatile("cp.async.cg.shared.global [%0], [%1], 16, %2;\n"
                 :: "r"(dst), "l"(src), "r"(sz));
}
__device__ __forceinline__ void ldsm_x4(uint32_t* r, unsigned addr)
{
    asm volatile("ldmatrix.sync.aligned.m8n8.x4.shared.b16 {%0,%1,%2,%3}, [%4];"
                 : "=r"(r[0]), "=r"(r[1]), "=r"(r[2]), "=r"(r[3]) : "r"(addr));
}
__device__ __forceinline__ void mma8(float* c, const uint32_t* a, const uint32_t* b)
{
    asm volatile(
        "mma.sync.aligned.m16n8k8.row.col.f32.tf32.tf32.f32 "
        "{%0,%1,%2,%3}, {%4,%5,%6,%7}, {%8,%9}, {%0,%1,%2,%3};"
        : "+f"(c[0]), "+f"(c[1]), "+f"(c[2]), "+f"(c[3])
        : "r"(a[0]), "r"(a[1]), "r"(a[2]), "r"(a[3]), "r"(b[0]), "r"(b[1]));
}

// ---------------------------------------------------------------------------
// TF32 GEMM: C[M,N] = alpha*A[M,K]*B[N,K]^T (+bias), 128x128x32, 3-stage.
// M % 128 == 0 assumed.
// ---------------------------------------------------------------------------
__global__ __launch_bounds__(256, 2) void mma_bt(
    const float* __restrict__ A, const float* __restrict__ B, float* __restrict__ C,
    int M, int N, int K, int lda, int ldb, int ldc,
    ll sAb, ll sBb, ll sCb,
    const float* __restrict__ bias, ll sBiasb, float alpha)
{
    constexpr int BM = 128, BN = 128, BK = 32, AP = 36;
    constexpr int ASZ = BM * AP;
    constexpr int STG = 2 * ASZ;

    extern __shared__ float sm[];

    A += (ll)blockIdx.z * sAb;
    B += (ll)blockIdx.z * sBb;
    C += (ll)blockIdx.z * sCb;
    if (bias) bias += (ll)blockIdx.z * sBiasb;

    const int m0 = blockIdx.y * BM, n0 = blockIdx.x * BN;
    const int tid = threadIdx.x, lane = tid & 31, warp = tid >> 5;
    const int g = lane >> 2, tg = lane & 3;
    const int wm = (warp & 1) * 64, wn = (warp >> 1) * 32;

    const int lm   = lane >> 3;
    const int lrow = (lm & 1) * 8 + (lane & 7);
    const int lcol = (lm >> 1) * 4;

    float acc[4][4][4] = {};
    const int nk = (K + BK - 1) / BK;

    auto load_stage = [&](int s, int k0) {
        unsigned base = smem_u32(sm + s * STG);
        #pragma unroll
        for (int i = 0; i < 4; i++) {
            int idx = tid + i * 256;
            int r = idx >> 3, c = (idx & 7) * 4;
            cp_async16(base + (unsigned)(r * AP + c) * 4,
                       A + (size_t)(m0 + r) * lda + k0 + c, (k0 + c < K));
        }
        #pragma unroll
        for (int i = 0; i < 4; i++) {
            int idx = tid + i * 256;
            int r = idx >> 3, c = (idx & 7) * 4;
            bool v = (n0 + r < N) && (k0 + c < K);
            cp_async16(base + (unsigned)(ASZ + r * AP + c) * 4,
                       B + (size_t)(n0 + r) * ldb + k0 + c, v);
        }
        asm volatile("cp.async.commit_group;");
    };

    load_stage(0, 0);
    if (nk > 1) load_stage(1, BK);

    for (int kt = 0; kt < nk; kt++) {
        int s = kt % 3;
        if (kt + 1 < nk) asm volatile("cp.async.wait_group 1;");
        else             asm volatile("cp.async.wait_group 0;");
        __syncthreads();

        if (kt + 2 < nk) load_stage((kt + 2) % 3, (kt + 2) * BK);

        unsigned aBase = smem_u32(sm + s * STG)
                       + (unsigned)((wm + lrow) * AP + lcol) * 4;
        unsigned bBase = smem_u32(sm + s * STG + ASZ)
                       + (unsigned)((wn + lrow) * AP + lcol) * 4;

        #pragma unroll
        for (int kk = 0; kk < BK; kk += 8) {
            uint32_t ar[4][4];
            #pragma unroll
            for (int mt = 0; mt < 4; mt++)
                ldsm_x4(ar[mt], aBase + (unsigned)(mt * 16 * AP + kk) * 4);
            uint32_t brq[2][4];
            #pragma unroll
            for (int nh = 0; nh < 2; nh++)
                ldsm_x4(brq[nh], bBase + (unsigned)(nh * 16 * AP + kk) * 4);

            #pragma unroll
            for (int mt = 0; mt < 4; mt++) {
                #pragma unroll
                for (int nt = 0; nt < 4; nt++) {
                    uint32_t bb[2] = { brq[nt >> 1][nt & 1], brq[nt >> 1][(nt & 1) + 2] };
                    mma8(acc[mt][nt], ar[mt], bb);
                }
            }
        }
    }

    #pragma unroll
    for (int mt = 0; mt < 4; mt++) {
        #pragma unroll
        for (int nt = 0; nt < 4; nt++) {
            int row0 = m0 + wm + mt * 16 + g;
            int col  = n0 + wn + nt * 8 + 2 * tg;
            if (col + 1 < N) {
                float b0 = bias ? bias[col]     : 0.f;
                float b1 = bias ? bias[col + 1] : 0.f;
                float2 v0 = make_float2(alpha * acc[mt][nt][0] + b0,
                                        alpha * acc[mt][nt][1] + b1);
                float2 v1 = make_float2(alpha * acc[mt][nt][2] + b0,
                                        alpha * acc[mt][nt][3] + b1);
                *reinterpret_cast<float2*>(C + (size_t)row0 * ldc + col) = v0;
                *reinterpret_cast<float2*>(C + (size_t)(row0 + 8) * ldc + col) = v1;
            } else if (col < N) {
                float b0 = bias ? bias[col] : 0.f;
                C[(size_t)row0 * ldc + col]       = alpha * acc[mt][nt][0] + b0;
                C[(size_t)(row0 + 8) * ldc + col] = alpha * acc[mt][nt][2] + b0;
            }
        }
    }
}

// ---------------------------------------------------------------------------
__device__ __forceinline__ float warp_max(float v) {
    #pragma unroll
    for (int o = 16; o > 0; o >>= 1) v = fmaxf(v, __shfl_xor_sync(0xffffffffu, v, o));
    return v;
}
__device__ __forceinline__ float warp_sum(float v) {
    #pragma unroll
    for (int o = 16; o > 0; o >>= 1) v += __shfl_xor_sync(0xffffffffu, v, o);
    return v;
}

__global__ __launch_bounds__(256) void softmax_kernel(float* __restrict__ Sm)
{
    size_t off = ((size_t)blockIdx.y * SEQ + blockIdx.x) * SEQ;
    float4* row4 = reinterpret_cast<float4*>(Sm + off);
    const int t = threadIdx.x;
    const int lane = t & 31, wid = t >> 5;

    float4 v[4];
    #pragma unroll
    for (int i = 0; i < 4; i++) v[i] = row4[t + 256 * i];

    float m = -3.4e38f;
    #pragma unroll
    for (int i = 0; i < 4; i++)
        m = fmaxf(m, fmaxf(fmaxf(v[i].x, v[i].y), fmaxf(v[i].z, v[i].w)));

    __shared__ float red[8];
    m = warp_max(m);
    if (lane == 0) red[wid] = m;
    __syncthreads();
    float bm = red[0];
    #pragma unroll
    for (int k = 1; k < 8; k++) bm = fmaxf(bm, red[k]);

    float s = 0.f;
    #pragma unroll
    for (int i = 0; i < 4; i++) {
        v[i].x = __expf(v[i].x - bm); v[i].y = __expf(v[i].y - bm);
        v[i].z = __expf(v[i].z - bm); v[i].w = __expf(v[i].w - bm);
        s += v[i].x + v[i].y + v[i].z + v[i].w;
    }
    s = warp_sum(s);
    __syncthreads();
    if (lane == 0) red[wid] = s;
    __syncthreads();
    float bs = 0.f;
    #pragma unroll
    for (int k = 0; k < 8; k++) bs += red[k];
    float inv = 1.f / bs;

    #pragma unroll
    for (int i = 0; i < 4; i++) {
        v[i].x *= inv; v[i].y *= inv; v[i].z *= inv; v[i].w *= inv;
        row4[t + 256 * i] = v[i];
    }
}

// ---------------------------------------------------------------------------
__global__ __launch_bounds__(128) void ln_add_kernel(
    const float* __restrict__ s1, const float* __restrict__ s2,
    const float* __restrict__ g, const float* __restrict__ b,
    float* __restrict__ dst)
{
    const int wid = threadIdx.x >> 5, lane = threadIdx.x & 31;
    const int row = blockIdx.x * 4 + wid;
    const size_t base = ((size_t)blockIdx.y * SEQ + row) * VECT;

    float v[10];
    float s = 0.f;
    #pragma unroll
    for (int i = 0; i < 10; i++) {
        int j = lane + 32 * i;
        float x = 0.f;
        if (j < VECT) x = s1[base + j] + s2[base + j];
        v[i] = x; s += x;
    }
    s = warp_sum(s);
    float mean = s * (1.f / VECT);

    float var = 0.f;
    #pragma unroll
    for (int i = 0; i < 10; i++) {
        int j = lane + 32 * i;
        if (j < VECT) { float d = v[i] - mean; var += d * d; }
    }
    var = warp_sum(var) * (1.f / VECT);
    float inv = rsqrtf(var + 1e-5f);

    #pragma unroll
    for (int i = 0; i < 10; i++) {
        int j = lane + 32 * i;
        if (j < VECT) dst[base + j] = g[j] * (v[i] - mean) * inv + b[j];
    }
}

// ---------------------------------------------------------------------------
// GRU recurrence. 2 blocks (one per GRU), 384 threads.
// Gate-parallel: thread t owns w_hh row t (gate = t>>7). r/z threads compute
// their sigmoid right after their own dot product (pre-barrier, overlapped
// with other warps' FMA issue); n-threads own h in registers and run the
// only post-barrier phase. Per-thread gx read via early __ldg (latency hidden
// under the 384-cycle dot phase).
// ---------------------------------------------------------------------------
__global__ __launch_bounds__(384, 1) void gru_kernel(
    const float* __restrict__ whh1, const float* __restrict__ bhh1,
    const float* __restrict__ whh2, const float* __restrict__ bhh2)
{
    const int b = blockIdx.x;
    const float* whh = b ? whh2 : whh1;
    const float* bhh = b ? bhh2 : bhh1;
    const float* gx  = g_gx + (size_t)b * SEQ * G3;
    const int t = threadIdx.x;
    const int gate = t >> 7;         // 0=r, 1=z, 2=n
    const int hid  = t & 127;

    ull wp[64];
    const ull* w2 = reinterpret_cast<const ull*>(whh + t * HID);
    #pragma unroll
    for (int j = 0; j < 64; j++) wp[j] = w2[j];
    const float bh = bhh[t];

    __shared__ __align__(16) float hsh[HID];
    __shared__ float rsh[HID];
    __shared__ float zsh[HID];

    float hcur = 0.f;                 // live only in n-threads
    if (t < HID) hsh[t] = 0.f;
    __syncthreads();

    const float* gxp = gx + t;

    #pragma unroll 1
    for (int step = 0; step < SEQ; step++) {
        // early input load — consumed ~384 cycles later
        float xv = __ldg(gxp + (size_t)step * G3);

        // gh_t = dot(whh_t, h) + bhh_t  (4 independent FFMA2 chains)
        ull a0 = 0ull, a1 = 0ull, a2 = 0ull, a3 = 0ull;
        const ulonglong2* h2 = reinterpret_cast<const ulonglong2*>(hsh);
        #pragma unroll
        for (int j = 0; j < 16; j++) {
            ulonglong2 hva = h2[2 * j];
            ulonglong2 hvb = h2[2 * j + 1];
            asm("fma.rn.f32x2 %0, %1, %2, %0;" : "+l"(a0) : "l"(wp[4 * j]),     "l"(hva.x));
            asm("fma.rn.f32x2 %0, %1, %2, %0;" : "+l"(a1) : "l"(wp[4 * j + 1]), "l"(hva.y));
            asm("fma.rn.f32x2 %0, %1, %2, %0;" : "+l"(a2) : "l"(wp[4 * j + 2]), "l"(hvb.x));
            asm("fma.rn.f32x2 %0, %1, %2, %0;" : "+l"(a3) : "l"(wp[4 * j + 3]), "l"(hvb.y));
        }
        float l0, h0, l1, h1, l2, h2f, l3, h3;
        asm("mov.b64 {%0,%1}, %2;" : "=f"(l0), "=f"(h0) : "l"(a0));
        asm("mov.b64 {%0,%1}, %2;" : "=f"(l1), "=f"(h1) : "l"(a1));
        asm("mov.b64 {%0,%1}, %2;" : "=f"(l2), "=f"(h2f) : "l"(a2));
        asm("mov.b64 {%0,%1}, %2;" : "=f"(l3), "=f"(h3) : "l"(a3));
        float ghv = ((l0 + h0) + (l1 + h1)) + ((l2 + h2f) + (l3 + h3)) + bh;

        // r/z: finish gate pre-barrier (overlaps other warps' FMA issue)
        if (gate == 0) {
            rsh[hid] = __fdividef(1.f, 1.f + __expf(-(xv + ghv)));
        } else if (gate == 1) {
            zsh[hid] = __fdividef(1.f, 1.f + __expf(-(xv + ghv)));
        }
        __syncthreads();

        // n-threads: tanh + state update (h lives in their registers)
        if (gate == 2) {
            float r = rsh[hid], z = zsh[hid];
            float narg = xv + r * ghv;
            float e2 = __expf(2.f * narg);
            float n = 1.f - __fdividef(2.f, e2 + 1.f);
            hcur = n + z * (hcur - n);
            hsh[hid] = hcur;
        }
        __syncthreads();
    }
    if (gate == 2) g_hcat[b * HID + hid] = hcur;
}

// ---------------------------------------------------------------------------
__global__ __launch_bounds__(256) void head_kernel(
    const float* __restrict__ fc1_w, const float* __restrict__ fc1_b,
    const float* __restrict__ fc2_w, const float* __restrict__ fc2_b,
    float* __restrict__ out)
{
    __shared__ float hs[256], ys[256], ls[3];
    const int t = threadIdx.x;
    hs[t] = g_hcat[t];
    __syncthreads();

    float acc = fc1_b[t];
    #pragma unroll 8
    for (int j = 0; j < 256; j++) acc += fc1_w[t * 256 + j] * hs[j];
    ys[t] = fmaxf(acc, 0.f);
    __syncthreads();

    if (t < 3) {
        float a = fc2_b[t];
        for (int j = 0; j < 256; j++) a += fc2_w[t * 256 + j] * ys[j];
        ls[t] = a;
    }
    __syncthreads();

    if (t == 0) {
        float m = fmaxf(ls[0], fmaxf(ls[1], ls[2]));
        float s = expf(ls[0] - m) + expf(ls[1] - m) + expf(ls[2] - m);
        float lse = m + logf(s);
        out[0] = ls[0] - lse; out[1] = ls[1] - lse; out[2] = ls[2] - lse;
    }
}

// ---------------------------------------------------------------------------
extern "C" void kernel_launch(void* const* d_in, const int* in_sizes, int n_in,
                              void* d_out, int out_size)
{
    (void)in_sizes; (void)n_in; (void)out_size;

    const float* x1     = (const float*)d_in[0];
    const float* x2     = (const float*)d_in[1];
    const float* q_w    = (const float*)d_in[2];
    const float* q_b    = (const float*)d_in[3];
    const float* k_w    = (const float*)d_in[4];
    const float* k_b    = (const float*)d_in[5];
    const float* v_w    = (const float*)d_in[6];
    const float* v_b    = (const float*)d_in[7];
    const float* aln_g  = (const float*)d_in[8];
    const float* aln_b  = (const float*)d_in[9];
    const float* w_w    = (const float*)d_in[10];
    const float* w_b    = (const float*)d_in[11];
    const float* mln_g  = (const float*)d_in[12];
    const float* mln_b  = (const float*)d_in[13];
    const float* g1_wih = (const float*)d_in[14];
    const float* g1_whh = (const float*)d_in[15];
    const float* g1_bih = (const float*)d_in[16];
    const float* g1_bhh = (const float*)d_in[17];
    const float* g2_wih = (const float*)d_in[18];
    const float* g2_whh = (const float*)d_in[19];
    const float* g2_bih = (const float*)d_in[20];
    const float* g2_bhh = (const float*)d_in[21];
    const float* fc1_w  = (const float*)d_in[22];
    const float* fc1_b  = (const float*)d_in[23];
    const float* fc2_w  = (const float*)d_in[24];
    const float* fc2_b  = (const float*)d_in[25];
    float* out = (float*)d_out;

    void *pv;
    cudaGetSymbolAddress(&pv, g_x);      float* p_x      = (float*)pv;
    cudaGetSymbolAddress(&pv, g_cur);    float* p_cur    = (float*)pv;
    cudaGetSymbolAddress(&pv, g_qkv);    float* p_qkv    = (float*)pv;
    cudaGetSymbolAddress(&pv, g_vt);     float* p_vt     = (float*)pv;
    cudaGetSymbolAddress(&pv, g_attn);   float* p_attn   = (float*)pv;
    cudaGetSymbolAddress(&pv, g_h);      float* p_h      = (float*)pv;
    cudaGetSymbolAddress(&pv, g_tmp);    float* p_tmp    = (float*)pv;
    cudaGetSymbolAddress(&pv, g_scores); float* p_scores = (float*)pv;
    cudaGetSymbolAddress(&pv, g_gx);     float* p_gx     = (float*)pv;
    cudaGetSymbolAddress(&pv, g_wqkv);   float* p_wqkv   = (float*)pv;
    cudaGetSymbolAddress(&pv, g_bqkv);   float* p_bqkv   = (float*)pv;
    cudaGetSymbolAddress(&pv, g_wih);    float* p_wih    = (float*)pv;
    cudaGetSymbolAddress(&pv, g_bih);    float* p_bih    = (float*)pv;

    const ll SV = (ll)SEQ * VECT;
    const ll S9 = (ll)SEQ * 3 * VECT;
    const ll SS = (ll)SEQ * SEQ;
    const int N9 = 3 * VECT;
    const float inv_scale = 0.05773502691896258f;   // 1/sqrt(300)

    const int SMEM_MMA = 3 * (2 * 128 * 36) * 4;    // 110592 B
    cudaFuncSetAttribute(mma_bt, cudaFuncAttributeMaxDynamicSharedMemorySize, SMEM_MMA);

    init_kernel<<<(2 * SEQ * VECT + 255) / 256, 256>>>(x1, x2);
    {
        int tot = 3 * VECT * VECT + 3 * VECT + 2 * G3 * VECT + 2 * G3;
        pack_kernel<<<(tot + 255) / 256, 256>>>(q_w, q_b, k_w, k_b, v_w, v_b,
                                                g1_wih, g1_bih, g2_wih, g2_bih);
    }

    dim3 gqkv(8, 32, 2);    // QKV proj: N=900 -> 8 tiles of 128
    dim3 gqk (32, 32, 2);   // QK^T: 4096x4096
    dim3 gav (3, 32, 2);    // A·V: N=300
    dim3 gw  (3, 32, 2);    // W proj
    dim3 gtr (10, 128, 2);  // V transpose

    for (int s = 0; s < NSTACK; s++) {
        mma_bt<<<gqkv, 256, SMEM_MMA>>>(p_cur, p_wqkv, p_qkv, SEQ, N9, VECT,
                                        VECT, VECT, N9, SV, 0, S9,
                                        p_bqkv, 0, 1.f);
        mma_bt<<<gqk, 256, SMEM_MMA>>>(p_qkv, p_qkv + VECT, p_scores, SEQ, SEQ, VECT,
                                       N9, N9, SEQ, S9, S9, SS,
                                       nullptr, 0, inv_scale);
        softmax_kernel<<<dim3(SEQ, 2), 256>>>(p_scores);

        transpose_kernel<<<gtr, 256>>>(p_qkv + 2 * VECT, p_vt, N9, S9, SV);
        mma_bt<<<gav, 256, SMEM_MMA>>>(p_scores, p_vt, p_attn, SEQ, VECT, SEQ,
                                       SEQ, SEQ, VECT, SS, SV, SV,
                                       nullptr, 0, 1.f);

        ln_add_kernel<<<dim3(SEQ / 4, 2), 128>>>(p_attn, p_cur, aln_g, aln_b, p_h);
        mma_bt<<<gw, 256, SMEM_MMA>>>(p_h, w_w, p_tmp, SEQ, VECT, VECT,
                                      VECT, VECT, VECT, SV, 0, SV,
                                      w_b, 0, 1.f);
        ln_add_kernel<<<dim3(SEQ / 4, 2), 128>>>(p_tmp, p_x, mln_g, mln_b, p_cur);
    }

    dim3 gg(3, 32, 2);
    mma_bt<<<gg, 256, SMEM_MMA>>>(p_cur, p_wih, p_gx, SEQ, G3, VECT,
                                  VECT, VECT, G3, SV, (ll)G3 * VECT, (ll)SEQ * G3,
                                  p_bih, G3, 1.f);
    gru_kernel<<<2, 384>>>(g1_whh, g1_bhh, g2_whh, g2_bhh);
    head_kernel<<<1, 256>>>(fc1_w, fc1_b, fc2_w, fc2_b, out);
}